// round 13
// baseline (speedup 1.0000x reference)
#include <cuda_runtime.h>
#include <cuda_bf16.h>
#include <mma.h>
#include <math.h>
#include <stdint.h>

using namespace nvcuda;

#define BB 4
#define SS 256
#define VV 64
#define LP1 11
#define HH 128
#define NHH 8
#define DHH 16
#define NLL 3
#define BT 1024   // B*S
#define HS (HH * HH)

typedef unsigned long long u64;

// ---------------- scratch (static device globals; no runtime allocation) ----
__device__ float g_adj[VV * VV * LP1];
__device__ __nv_bfloat16 g_Whi[7L * VV * HS];
__device__ __nv_bfloat16 g_Wlo[7L * VV * HS];
__device__ __nv_bfloat16 g_zhi0[(long)VV * BT * HH];
__device__ __nv_bfloat16 g_zlo0[(long)VV * BT * HH];
__device__ __nv_bfloat16 g_zhi1[(long)VV * BT * HH];
__device__ __nv_bfloat16 g_zlo1[(long)VV * BT * HH];
__device__ __nv_bfloat16 g_ohi[(long)VV * BT * HH];
__device__ __nv_bfloat16 g_olo[(long)VV * BT * HH];
__device__ float g_qb[(long)VV * BT * HH];
__device__ float g_kb[(long)VV * BT * HH];
__device__ float g_vb[(long)VV * BT * HH];
__device__ float g_z0[(long)VV * BT * HH];

// ---------------- helpers ----------------------------------------------------
__device__ __forceinline__ float ex2a(float x) {
    float r; asm("ex2.approx.f32 %0, %1;" : "=f"(r) : "f"(x)); return r;
}
__device__ __forceinline__ void split_store2(
    __nv_bfloat16* hi, __nv_bfloat16* lo, int idx, float a, float b)
{
    __nv_bfloat16 ha = __float2bfloat16(a), hb = __float2bfloat16(b);
    __nv_bfloat16 la = __float2bfloat16(a - __bfloat162float(ha));
    __nv_bfloat16 lb = __float2bfloat16(b - __bfloat162float(hb));
    *(__nv_bfloat162*)&hi[idx] = __nv_bfloat162{ha, hb};
    *(__nv_bfloat162*)&lo[idx] = __nv_bfloat162{la, lb};
}

#define CPA16(smaddr, gptr) \
    asm volatile("cp.async.cg.shared.global [%0], [%1], 16;" :: "r"(smaddr), "l"(gptr))

// ---------------- kernel 0: sigmoid of adjacency logits ---------------------
__global__ void sigmoid_kernel(const float* __restrict__ logits, float* __restrict__ adj, int n) {
    int i = blockIdx.x * blockDim.x + threadIdx.x;
    if (i < n) {
        float x = logits[i];
        adj[i] = 1.f / (1.f + __expf(-x));
    }
}

// ---------------- kernel 0b: split all weights to bf16 hi/lo ----------------
__global__ void split_weights_kernel(
    const float* __restrict__ mechW, const float* __restrict__ Wq,
    const float* __restrict__ Wk, const float* __restrict__ Wv,
    const float* __restrict__ Wo,
    __nv_bfloat16* __restrict__ hi, __nv_bfloat16* __restrict__ lo)
{
    long i = (long)blockIdx.x * blockDim.x + threadIdx.x;
    if (i >= 7L * VV * HS) return;
    int mat = (int)(i / ((long)VV * HS));
    long rem = i % ((long)VV * HS);
    int v = (int)(rem / HS);
    int e = (int)(rem % HS);
    float x;
    if (mat < 3) x = mechW[((long)v * NLL + mat) * HS + e];
    else {
        const float* p = (mat == 3) ? Wq : (mat == 4) ? Wk : (mat == 5) ? Wv : Wo;
        x = p[(long)v * HS + e];
    }
    __nv_bfloat16 h = __float2bfloat16(x);
    hi[i] = h;
    lo[i] = __float2bfloat16(x - __bfloat162float(h));
}

// ---------------- kernel 1: causal input z[b,t,i,h] -> bf16 hi/lo -----------
__global__ void __launch_bounds__(128) causal_input_kernel(
    const float* __restrict__ x,
    const float* __restrict__ var_emb,
    const float* __restrict__ temp_emb,
    const float* __restrict__ adj,
    __nv_bfloat16* __restrict__ zHi, __nv_bfloat16* __restrict__ zLo)
{
    __shared__ float xlag[VV][12];
    __shared__ float Asm[VV][65];
    __shared__ float Blsm[VV][12];

    int bt = blockIdx.x;
    int b = bt >> 8;
    int t = bt & 255;
    int tid = threadIdx.x;

    for (int i = tid; i < VV * LP1; i += 128) {
        int s = i / LP1, l = i % LP1;
        xlag[s][l] = (t >= l) ? x[(b * SS + (t - l)) * VV + s] : 0.f;
    }
    __syncthreads();

    for (int i = tid; i < VV * VV; i += 128) {
        int s = i >> 6, ii = i & 63;
        const float* ap = adj + (s * VV + ii) * LP1;
        float a = 0.f;
#pragma unroll
        for (int l = 0; l < LP1; l++) a += xlag[s][l] * ap[l];
        Asm[ii][s] = a;
    }
    for (int i = tid; i < VV * LP1; i += 128) {
        int ii = i / LP1, l = i % LP1;
        float a = 0.f;
#pragma unroll 8
        for (int s = 0; s < VV; s++) a += xlag[s][l] * adj[(s * VV + ii) * LP1 + l];
        Blsm[ii][l] = a;
    }
    __syncthreads();

    int h = tid;  // 128 threads == H
    float acc[VV];
#pragma unroll
    for (int ii = 0; ii < VV; ii++) acc[ii] = 0.f;
    for (int s = 0; s < VV; s++) {
        float ve = var_emb[s * HH + h];
#pragma unroll
        for (int ii = 0; ii < VV; ii++) acc[ii] += Asm[ii][s] * ve;
    }
#pragma unroll
    for (int l = 0; l < LP1; l++) {
        float te = temp_emb[l * HH + h];
#pragma unroll
        for (int ii = 0; ii < VV; ii++) acc[ii] += Blsm[ii][l] * te;
    }
#pragma unroll 8
    for (int ii = 0; ii < VV; ii++) {
        long o = ((long)ii * BT + bt) * HH + h;
        __nv_bfloat16 hh = __float2bfloat16(acc[ii]);
        zHi[o] = hh;
        zLo[o] = __float2bfloat16(acc[ii] - __bfloat162float(hh));
    }
}

// ---------------- kernel 2: per-variable GEMM on tensor cores ---------------
#define A_LD 40
#define B_LD 136
#define E_LD 132
#define ABUF 20480
#define BBUF 17408
#define PV_SMEM_BYTES 75776

template <bool LN_GELU, bool OUT_SPLIT>
__global__ void __launch_bounds__(256, 2) pv_gemm(
    const __nv_bfloat16* __restrict__ Ahi, const __nv_bfloat16* __restrict__ Alo,
    const __nv_bfloat16* __restrict__ Whi, const __nv_bfloat16* __restrict__ Wlo,
    const float* __restrict__ biasB, int bStride,
    const float* __restrict__ gB, const float* __restrict__ betaB,
    float* __restrict__ outF,
    __nv_bfloat16* __restrict__ outHi, __nv_bfloat16* __restrict__ outLo)
{
    extern __shared__ char smem[];
    float* Esm = (float*)smem;

    int v = blockIdx.y;
    int row0 = blockIdx.x * 128;
    const __nv_bfloat16* AhV = Ahi + ((long)v * BT + row0) * HH;
    const __nv_bfloat16* AlV = Alo + ((long)v * BT + row0) * HH;
    const __nv_bfloat16* WhV = Whi + (long)v * HS;
    const __nv_bfloat16* WlV = Wlo + (long)v * HS;
    const float* bias = biasB + (long)v * bStride;

    int tid = threadIdx.x;
    int w = tid >> 5;
    int wr = w >> 2;
    int wc = w & 3;

    unsigned int smem_u32;
    asm("{ .reg .u64 t0; cvta.to.shared.u64 t0, %1; cvt.u32.u64 %0, t0; }"
        : "=r"(smem_u32) : "l"(smem));

    int tA_r = tid >> 2, tA_g = tid & 3;
    int tB_r = tid >> 4, tB_g = tid & 15;
    unsigned int aOff0 = (unsigned int)(tA_r * A_LD + tA_g * 8) * 2u;
    unsigned int aOff1 = (unsigned int)((tA_r + 64) * A_LD + tA_g * 8) * 2u;
    unsigned int bOff0 = (unsigned int)(tB_r * B_LD + tB_g * 8) * 2u;
    unsigned int bOff1 = (unsigned int)((tB_r + 16) * B_LD + tB_g * 8) * 2u;

    auto issue_chunk = [&](int kt, int buf) {
        unsigned int aBase = smem_u32 + buf * ABUF;
        unsigned int bBase = smem_u32 + 2 * ABUF + buf * BBUF;
        const __nv_bfloat16* gah = AhV + (long)tA_r * HH + kt * 32 + tA_g * 8;
        const __nv_bfloat16* gal = AlV + (long)tA_r * HH + kt * 32 + tA_g * 8;
        CPA16(aBase + aOff0, gah);
        CPA16(aBase + aOff1, gah + 64 * HH);
        CPA16(aBase + 10240 + aOff0, gal);
        CPA16(aBase + 10240 + aOff1, gal + 64 * HH);
        const __nv_bfloat16* gwh = WhV + (long)(kt * 32 + tB_r) * HH + tB_g * 8;
        const __nv_bfloat16* gwl = WlV + (long)(kt * 32 + tB_r) * HH + tB_g * 8;
        CPA16(bBase + bOff0, gwh);
        CPA16(bBase + bOff1, gwh + 16 * HH);
        CPA16(bBase + 8704 + bOff0, gwl);
        CPA16(bBase + 8704 + bOff1, gwl + 16 * HH);
        asm volatile("cp.async.commit_group;");
    };

    wmma::fragment<wmma::accumulator, 16, 16, 16, float> acc[4][2];
#pragma unroll
    for (int i = 0; i < 4; i++)
#pragma unroll
        for (int j = 0; j < 2; j++) wmma::fill_fragment(acc[i][j], 0.f);

    issue_chunk(0, 0);
    issue_chunk(1, 1);

#pragma unroll
    for (int kt = 0; kt < 4; kt++) {
        if (kt < 3) { asm volatile("cp.async.wait_group 1;" ::: "memory"); }
        else        { asm volatile("cp.async.wait_group 0;" ::: "memory"); }
        __syncthreads();

        int buf = kt & 1;
        const __nv_bfloat16* Ah = (const __nv_bfloat16*)(smem + buf * ABUF);
        const __nv_bfloat16* Al = (const __nv_bfloat16*)(smem + buf * ABUF + 10240);
        const __nv_bfloat16* Bh = (const __nv_bfloat16*)(smem + 2 * ABUF + buf * BBUF);
        const __nv_bfloat16* Bl = (const __nv_bfloat16*)(smem + 2 * ABUF + buf * BBUF + 8704);

#pragma unroll
        for (int ks = 0; ks < 2; ks++) {
            wmma::fragment<wmma::matrix_a, 16, 16, 16, __nv_bfloat16, wmma::row_major> afh[4], afl[4];
            wmma::fragment<wmma::matrix_b, 16, 16, 16, __nv_bfloat16, wmma::row_major> bfh[2], bfl[2];
#pragma unroll
            for (int i = 0; i < 4; i++) {
                wmma::load_matrix_sync(afh[i], &Ah[(wr * 64 + i * 16) * A_LD + ks * 16], A_LD);
                wmma::load_matrix_sync(afl[i], &Al[(wr * 64 + i * 16) * A_LD + ks * 16], A_LD);
            }
#pragma unroll
            for (int j = 0; j < 2; j++) {
                wmma::load_matrix_sync(bfh[j], &Bh[(ks * 16) * B_LD + wc * 32 + j * 16], B_LD);
                wmma::load_matrix_sync(bfl[j], &Bl[(ks * 16) * B_LD + wc * 32 + j * 16], B_LD);
            }
#pragma unroll
            for (int i = 0; i < 4; i++)
#pragma unroll
                for (int j = 0; j < 2; j++) {
                    wmma::mma_sync(acc[i][j], afh[i], bfh[j], acc[i][j]);
                    wmma::mma_sync(acc[i][j], afh[i], bfl[j], acc[i][j]);
                    wmma::mma_sync(acc[i][j], afl[i], bfh[j], acc[i][j]);
                }
        }
        __syncthreads();
        if (kt < 2) issue_chunk(kt + 2, buf);
    }

#pragma unroll
    for (int i = 0; i < 4; i++)
#pragma unroll
        for (int j = 0; j < 2; j++)
            wmma::store_matrix_sync(&Esm[(wr * 64 + i * 16) * E_LD + wc * 32 + j * 16],
                                    acc[i][j], E_LD, wmma::mem_row_major);
    __syncthreads();

    int row = tid >> 1;
    int ch = (tid & 1) * 64;
    const float* er = Esm + row * E_LD + ch;
    float vals[64];
#pragma unroll
    for (int i = 0; i < 16; i++) {
        float4 x = *(const float4*)&er[i * 4];
        vals[i * 4 + 0] = x.x; vals[i * 4 + 1] = x.y;
        vals[i * 4 + 2] = x.z; vals[i * 4 + 3] = x.w;
    }
#pragma unroll
    for (int i = 0; i < 64; i++) vals[i] += bias[ch + i];

    if (LN_GELU) {
        const float* gp = gB + (long)v * bStride;
        const float* bp = betaB + (long)v * bStride;
        float sum = 0.f, sq = 0.f;
#pragma unroll
        for (int i = 0; i < 64; i++) { sum += vals[i]; sq += vals[i] * vals[i]; }
        sum += __shfl_xor_sync(0xffffffffu, sum, 1);
        sq  += __shfl_xor_sync(0xffffffffu, sq, 1);
        float mu = sum * (1.f / 128.f);
        float var = sq * (1.f / 128.f) - mu * mu;
        float inv = rsqrtf(var + 1e-5f);
#pragma unroll
        for (int i = 0; i < 64; i++) {
            float xn = (vals[i] - mu) * inv * gp[ch + i] + bp[ch + i];
            vals[i] = 0.5f * xn * (1.f + erff(xn * 0.70710678118654752f));
        }
    }

    long rowIdx = ((long)v * BT + row0 + row) * HH + ch;
    if (OUT_SPLIT) {
        __nv_bfloat16 hv[64], lv[64];
#pragma unroll
        for (int i = 0; i < 64; i++) {
            __nv_bfloat16 h = __float2bfloat16(vals[i]);
            hv[i] = h;
            lv[i] = __float2bfloat16(vals[i] - __bfloat162float(h));
        }
#pragma unroll
        for (int g = 0; g < 8; g++) {
            *(uint4*)&outHi[rowIdx + g * 8] = *(uint4*)&hv[g * 8];
            *(uint4*)&outLo[rowIdx + g * 8] = *(uint4*)&lv[g * 8];
        }
    } else {
#pragma unroll
        for (int i = 0; i < 16; i++) {
            float4 s = make_float4(vals[i * 4], vals[i * 4 + 1], vals[i * 4 + 2], vals[i * 4 + 3]);
            *(float4*)&outF[rowIdx + i * 4] = s;
        }
    }
}

// ---------------- kernel 3: tensor-core attention per (b,v,head) ------------
// Split-bf16 3-product MMAs for QK^T and PV; shift-free softmax.
// All wmma ld values are multiples of 4 (fp32) / 8 (bf16); tile ptrs 32B-aligned.
// smem layout (bytes):
//  Qh 0, Ql 8192, Kh 16384, Kl 24576, Vh 32768, Vl 40960   (each 256x16 bf16)
//  Sch  @49152  : fp32 [256][68]  = 69632   (score chunk; Osum aliases, ld 20)
//  Phm  @118784 : bf16 [256][72]  = 36864
//  Plm  @155648 : bf16 [256][72]  = 36864   -> total 192512
#define QK_LD 16
#define S_LD 68
#define O_LD 20
#define P_LD 72
#define ATTN_SMEM 192512

__global__ void __launch_bounds__(256, 1) attn_mma_kernel(
    const float* __restrict__ q, const float* __restrict__ k,
    const float* __restrict__ vv,
    __nv_bfloat16* __restrict__ oHi, __nv_bfloat16* __restrict__ oLo)
{
    extern __shared__ char sm[];
    __nv_bfloat16* Qh = (__nv_bfloat16*)(sm);
    __nv_bfloat16* Ql = (__nv_bfloat16*)(sm + 8192);
    __nv_bfloat16* Kh = (__nv_bfloat16*)(sm + 16384);
    __nv_bfloat16* Kl = (__nv_bfloat16*)(sm + 24576);
    __nv_bfloat16* Vh = (__nv_bfloat16*)(sm + 32768);
    __nv_bfloat16* Vl = (__nv_bfloat16*)(sm + 40960);
    float* Sch = (float*)(sm + 49152);
    __nv_bfloat16* Phm = (__nv_bfloat16*)(sm + 118784);
    __nv_bfloat16* Plm = (__nv_bfloat16*)(sm + 155648);
    float* Osum = (float*)(sm + 49152);   // alias over Sch after mainloop

    int g = blockIdx.x;
    int b = g / (VV * NHH);
    int rem = g % (VV * NHH);
    int v = rem / NHH;
    int nh = rem % NHH;
    long base = ((long)v * BT + (long)b * SS) * HH + nh * DHH;

    int tid = threadIdx.x;
    int w = tid >> 5;
    int lane = tid & 31;

    // ---- stage + split Q,K,V (row per thread) ----
    {
        int r = tid;
        const float* qp = q + base + (long)r * HH;
        const float* kp = k + base + (long)r * HH;
        const float* vp = vv + base + (long)r * HH;
#pragma unroll
        for (int i = 0; i < 4; i++) {
            float4 xq = *(const float4*)(qp + i * 4);
            float4 xk = *(const float4*)(kp + i * 4);
            float4 xv = *(const float4*)(vp + i * 4);
            split_store2(Qh, Ql, r * QK_LD + i * 4,     xq.x, xq.y);
            split_store2(Qh, Ql, r * QK_LD + i * 4 + 2, xq.z, xq.w);
            split_store2(Kh, Kl, r * QK_LD + i * 4,     xk.x, xk.y);
            split_store2(Kh, Kl, r * QK_LD + i * 4 + 2, xk.z, xk.w);
            split_store2(Vh, Vl, r * QK_LD + i * 4,     xv.x, xv.y);
            split_store2(Vh, Vl, r * QK_LD + i * 4 + 2, xv.z, xv.w);
        }
    }
    __syncthreads();

    // persistent Q fragments (rows w*32 .. w*32+31)
    wmma::fragment<wmma::matrix_a, 16, 16, 16, __nv_bfloat16, wmma::row_major> qfh[2], qfl[2];
#pragma unroll
    for (int i = 0; i < 2; i++) {
        wmma::load_matrix_sync(qfh[i], Qh + (w * 32 + i * 16) * QK_LD, QK_LD);
        wmma::load_matrix_sync(qfl[i], Ql + (w * 32 + i * 16) * QK_LD, QK_LD);
    }
    wmma::fragment<wmma::accumulator, 16, 16, 16, float> oacc[2];
#pragma unroll
    for (int i = 0; i < 2; i++) wmma::fill_fragment(oacc[i], 0.f);
    float lreg = 0.f;

    const float c0 = 0.25f * 1.4426950408889634f;  // scale * log2(e)

    for (int jc = 0; jc < 4; jc++) {
        int j0 = jc * 64;

        // ---- score chunk: S[w*32.., j0..j0+63] ----
        wmma::fragment<wmma::accumulator, 16, 16, 16, float> sacc[2][4];
#pragma unroll
        for (int i = 0; i < 2; i++)
#pragma unroll
            for (int ct = 0; ct < 4; ct++) wmma::fill_fragment(sacc[i][ct], 0.f);
#pragma unroll
        for (int ct = 0; ct < 4; ct++) {
            wmma::fragment<wmma::matrix_b, 16, 16, 16, __nv_bfloat16, wmma::col_major> kfh, kfl;
            wmma::load_matrix_sync(kfh, Kh + (j0 + ct * 16) * QK_LD, QK_LD);
            wmma::load_matrix_sync(kfl, Kl + (j0 + ct * 16) * QK_LD, QK_LD);
#pragma unroll
            for (int i = 0; i < 2; i++) {
                wmma::mma_sync(sacc[i][ct], qfh[i], kfh, sacc[i][ct]);
                wmma::mma_sync(sacc[i][ct], qfh[i], kfl, sacc[i][ct]);
                wmma::mma_sync(sacc[i][ct], qfl[i], kfh, sacc[i][ct]);
            }
        }
#pragma unroll
        for (int i = 0; i < 2; i++)
#pragma unroll
            for (int ct = 0; ct < 4; ct++)
                wmma::store_matrix_sync(&Sch[(w * 32 + i * 16) * S_LD + ct * 16],
                                        sacc[i][ct], S_LD, wmma::mem_row_major);
        __syncthreads();

        // ---- exp + split-store P + row sums (warp w owns rows w*32..+31) ----
#pragma unroll 4
        for (int ri = 0; ri < 32; ri++) {
            int r = w * 32 + ri;
            float2 sv = *(const float2*)&Sch[r * S_LD + lane * 2];
            float p0 = ex2a(sv.x * c0);
            float p1 = ex2a(sv.y * c0);
            float ps = p0 + p1;
#pragma unroll
            for (int m = 16; m; m >>= 1) ps += __shfl_xor_sync(0xffffffffu, ps, m);
            if (lane == ri) lreg += ps;
            split_store2(Phm, Plm, r * P_LD + lane * 2, p0, p1);
        }
        __syncthreads();

        // ---- O += P_chunk @ V_chunk ----
#pragma unroll
        for (int ks = 0; ks < 4; ks++) {
            wmma::fragment<wmma::matrix_b, 16, 16, 16, __nv_bfloat16, wmma::row_major> vfh, vfl;
            wmma::load_matrix_sync(vfh, Vh + (j0 + ks * 16) * QK_LD, QK_LD);
            wmma::load_matrix_sync(vfl, Vl + (j0 + ks * 16) * QK_LD, QK_LD);
#pragma unroll
            for (int i = 0; i < 2; i++) {
                wmma::fragment<wmma::matrix_a, 16, 16, 16, __nv_bfloat16, wmma::row_major> pfh, pfl;
                wmma::load_matrix_sync(pfh, Phm + (w * 32 + i * 16) * P_LD + ks * 16, P_LD);
                wmma::load_matrix_sync(pfl, Plm + (w * 32 + i * 16) * P_LD + ks * 16, P_LD);
                wmma::mma_sync(oacc[i], pfh, vfh, oacc[i]);
                wmma::mma_sync(oacc[i], pfh, vfl, oacc[i]);
                wmma::mma_sync(oacc[i], pfl, vfh, oacc[i]);
            }
        }
        __syncthreads();
    }

    // ---- output: scale by 1/l, split-bf16 store ----
#pragma unroll
    for (int i = 0; i < 2; i++)
        wmma::store_matrix_sync(&Osum[(w * 32 + i * 16) * O_LD], oacc[i], O_LD, wmma::mem_row_major);
    __syncthreads();
    {
        int r = tid;
        float invl = 1.f / lreg;
        __nv_bfloat16 hv[16], lv[16];
#pragma unroll
        for (int c = 0; c < 16; c++) {
            float o = Osum[r * O_LD + c] * invl;
            __nv_bfloat16 h = __float2bfloat16(o);
            hv[c] = h;
            lv[c] = __float2bfloat16(o - __bfloat162float(h));
        }
        long ob = base + (long)r * HH;
        *(uint4*)&oHi[ob]     = *(uint4*)&hv[0];
        *(uint4*)&oHi[ob + 8] = *(uint4*)&hv[8];
        *(uint4*)&oLo[ob]     = *(uint4*)&lv[0];
        *(uint4*)&oLo[ob + 8] = *(uint4*)&lv[8];
    }
}

// ---------------- kernel 4: output head predictions[b,t,v] ------------------
__global__ void __launch_bounds__(256) outhead_kernel(
    const float* __restrict__ o2,
    const float* __restrict__ outW, const float* __restrict__ outB,
    float* __restrict__ pred)
{
    int bt = blockIdx.x;
    int tid = threadIdx.x;
    int v = tid >> 2;
    int part = tid & 3;
    const float* row = o2 + ((long)v * BT + bt) * HH + part * 32;
    const float* w = outW + v * HH + part * 32;
    float acc = 0.f;
#pragma unroll 8
    for (int i = 0; i < 32; i++) acc += row[i] * w[i];
    acc += __shfl_xor_sync(0xffffffffu, acc, 1);
    acc += __shfl_xor_sync(0xffffffffu, acc, 2);
    if (part == 0) pred[bt * VV + v] = acc + outB[v];
}

// ---------------- launch ----------------------------------------------------
extern "C" void kernel_launch(void* const* d_in, const int* in_sizes, int n_in,
                              void* d_out, int out_size) {
    const float* x        = (const float*)d_in[0];
    const float* adjl     = (const float*)d_in[1];
    const float* var_emb  = (const float*)d_in[2];
    const float* temp_emb = (const float*)d_in[3];
    const float* mech_W   = (const float*)d_in[4];
    const float* mech_b   = (const float*)d_in[5];
    const float* ln_g     = (const float*)d_in[6];
    const float* ln_b     = (const float*)d_in[7];
    const float* Wq       = (const float*)d_in[8];
    const float* Wk       = (const float*)d_in[9];
    const float* Wv       = (const float*)d_in[10];
    const float* Wo       = (const float*)d_in[11];
    const float* bq       = (const float*)d_in[12];
    const float* bk       = (const float*)d_in[13];
    const float* bv       = (const float*)d_in[14];
    const float* bo       = (const float*)d_in[15];
    const float* out_W    = (const float*)d_in[16];
    const float* out_b    = (const float*)d_in[17];
    float* pred = (float*)d_out;

    float *adj, *qb, *kb, *vb, *z0;
    __nv_bfloat16 *Whi, *Wlo, *zhi0, *zlo0, *zhi1, *zlo1, *ohi, *olo;
    cudaGetSymbolAddress((void**)&adj, g_adj);
    cudaGetSymbolAddress((void**)&Whi, g_Whi);
    cudaGetSymbolAddress((void**)&Wlo, g_Wlo);
    cudaGetSymbolAddress((void**)&zhi0, g_zhi0);
    cudaGetSymbolAddress((void**)&zlo0, g_zlo0);
    cudaGetSymbolAddress((void**)&zhi1, g_zhi1);
    cudaGetSymbolAddress((void**)&zlo1, g_zlo1);
    cudaGetSymbolAddress((void**)&ohi, g_ohi);
    cudaGetSymbolAddress((void**)&olo, g_olo);
    cudaGetSymbolAddress((void**)&qb, g_qb);
    cudaGetSymbolAddress((void**)&kb, g_kb);
    cudaGetSymbolAddress((void**)&vb, g_vb);
    cudaGetSymbolAddress((void**)&z0, g_z0);

    static bool attr_done = false;
    if (!attr_done) {
        cudaFuncSetAttribute((const void*)pv_gemm<true, true>,
                             cudaFuncAttributeMaxDynamicSharedMemorySize, PV_SMEM_BYTES);
        cudaFuncSetAttribute((const void*)pv_gemm<false, false>,
                             cudaFuncAttributeMaxDynamicSharedMemorySize, PV_SMEM_BYTES);
        cudaFuncSetAttribute((const void*)attn_mma_kernel,
                             cudaFuncAttributeMaxDynamicSharedMemorySize, ATTN_SMEM);
        attr_done = true;
    }

    int nadj = VV * VV * LP1;
    sigmoid_kernel<<<(nadj + 255) / 256, 256>>>(adjl, adj, nadj);

    long nw = 7L * VV * HS;
    split_weights_kernel<<<(int)((nw + 255) / 256), 256>>>(mech_W, Wq, Wk, Wv, Wo, Whi, Wlo);

    causal_input_kernel<<<BT, 128>>>(x, var_emb, temp_emb, adj, zhi0, zlo0);

    dim3 gg(BT / 128, VV);
    const long WSZ = (long)VV * HS;
    pv_gemm<true, true><<<gg, 256, PV_SMEM_BYTES>>>(
        zhi0, zlo0, Whi + 0 * WSZ, Wlo + 0 * WSZ, mech_b + 0 * HH, NLL * HH,
        ln_g + 0 * HH, ln_b + 0 * HH, nullptr, zhi1, zlo1);
    pv_gemm<true, true><<<gg, 256, PV_SMEM_BYTES>>>(
        zhi1, zlo1, Whi + 1 * WSZ, Wlo + 1 * WSZ, mech_b + 1 * HH, NLL * HH,
        ln_g + 1 * HH, ln_b + 1 * HH, nullptr, zhi0, zlo0);
    pv_gemm<true, true><<<gg, 256, PV_SMEM_BYTES>>>(
        zhi0, zlo0, Whi + 2 * WSZ, Wlo + 2 * WSZ, mech_b + 2 * HH, NLL * HH,
        ln_g + 2 * HH, ln_b + 2 * HH, nullptr, zhi1, zlo1);
    pv_gemm<false, false><<<gg, 256, PV_SMEM_BYTES>>>(
        zhi1, zlo1, Whi + 3 * WSZ, Wlo + 3 * WSZ, bq, HH,
        nullptr, nullptr, qb, nullptr, nullptr);
    pv_gemm<false, false><<<gg, 256, PV_SMEM_BYTES>>>(
        zhi1, zlo1, Whi + 4 * WSZ, Wlo + 4 * WSZ, bk, HH,
        nullptr, nullptr, kb, nullptr, nullptr);
    pv_gemm<false, false><<<gg, 256, PV_SMEM_BYTES>>>(
        zhi1, zlo1, Whi + 5 * WSZ, Wlo + 5 * WSZ, bv, HH,
        nullptr, nullptr, vb, nullptr, nullptr);
    attn_mma_kernel<<<BB * VV * NHH, 256, ATTN_SMEM>>>(qb, kb, vb, ohi, olo);
    pv_gemm<false, false><<<gg, 256, PV_SMEM_BYTES>>>(
        ohi, olo, Whi + 6 * WSZ, Wlo + 6 * WSZ, bo, HH,
        nullptr, nullptr, z0, nullptr, nullptr);
    outhead_kernel<<<BT, 256>>>(z0, out_W, out_b, pred);
}

// round 14
// speedup vs baseline: 1.1449x; 1.1449x over previous
#include <cuda_runtime.h>
#include <cuda_bf16.h>
#include <mma.h>
#include <math.h>
#include <stdint.h>

using namespace nvcuda;

#define BB 4
#define SS 256
#define VV 64
#define LP1 11
#define HH 128
#define NHH 8
#define DHH 16
#define NLL 3
#define BT 1024   // B*S
#define HS (HH * HH)

typedef unsigned long long u64;

// ---------------- scratch (static device globals; no runtime allocation) ----
__device__ float g_adj[VV * VV * LP1];
__device__ __nv_bfloat16 g_Whi[7L * VV * HS];
__device__ __nv_bfloat16 g_Wlo[7L * VV * HS];
__device__ __nv_bfloat16 g_zhi0[(long)VV * BT * HH];
__device__ __nv_bfloat16 g_zlo0[(long)VV * BT * HH];
__device__ __nv_bfloat16 g_zhi1[(long)VV * BT * HH];
__device__ __nv_bfloat16 g_zlo1[(long)VV * BT * HH];
__device__ __nv_bfloat16 g_ohi[(long)VV * BT * HH];
__device__ __nv_bfloat16 g_olo[(long)VV * BT * HH];
__device__ float g_qb[(long)VV * BT * HH];
__device__ float g_kb[(long)VV * BT * HH];
__device__ float g_vb[(long)VV * BT * HH];
__device__ float g_z0[(long)VV * BT * HH];

// ---------------- packed f32x2 helpers --------------------------------------
__device__ __forceinline__ void fma2(u64& d, u64 a, u64 b) {
    asm("fma.rn.f32x2 %0, %1, %2, %3;" : "=l"(d) : "l"(a), "l"(b), "l"(d));
}
__device__ __forceinline__ u64 add2(u64 a, u64 b) {
    u64 r; asm("add.rn.f32x2 %0, %1, %2;" : "=l"(r) : "l"(a), "l"(b)); return r;
}
__device__ __forceinline__ u64 pack2(float lo, float hi) {
    u64 r; asm("mov.b64 %0, {%1, %2};" : "=l"(r) : "f"(lo), "f"(hi)); return r;
}
__device__ __forceinline__ void unpack2(u64 v, float& lo, float& hi) {
    asm("mov.b64 {%0, %1}, %2;" : "=f"(lo), "=f"(hi) : "l"(v));
}
__device__ __forceinline__ void split_store2(
    __nv_bfloat16* hi, __nv_bfloat16* lo, int idx, float a, float b)
{
    __nv_bfloat16 ha = __float2bfloat16(a), hb = __float2bfloat16(b);
    __nv_bfloat16 la = __float2bfloat16(a - __bfloat162float(ha));
    __nv_bfloat16 lb = __float2bfloat16(b - __bfloat162float(hb));
    *(__nv_bfloat162*)&hi[idx] = __nv_bfloat162{ha, hb};
    *(__nv_bfloat162*)&lo[idx] = __nv_bfloat162{la, lb};
}

// ---- fast exact-enough GELU: A&S 7.1.26 erf (|err| <= 1.5e-7 abs) ----------
__device__ __forceinline__ float fast_gelu(float x) {
    float z = fabsf(x) * 0.70710678118654752f;
    float t = __fdividef(1.f, 1.f + 0.3275911f * z);
    float poly = t * (0.254829592f + t * (-0.284496736f +
                 t * (1.421413741f + t * (-1.453152027f + t * 1.061405429f))));
    float erfz = 1.f - poly * __expf(-z * z);
    float erfx = copysignf(erfz, x);
    return 0.5f * x * (1.f + erfx);
}

#define CPA16(smaddr, gptr) \
    asm volatile("cp.async.cg.shared.global [%0], [%1], 16;" :: "r"(smaddr), "l"(gptr))

// ---------------- kernel 0: sigmoid of adjacency logits ---------------------
__global__ void sigmoid_kernel(const float* __restrict__ logits, float* __restrict__ adj, int n) {
    int i = blockIdx.x * blockDim.x + threadIdx.x;
    if (i < n) {
        float x = logits[i];
        adj[i] = 1.f / (1.f + __expf(-x));
    }
}

// ---------------- kernel 0b: split all weights to bf16 hi/lo ----------------
__global__ void split_weights_kernel(
    const float* __restrict__ mechW, const float* __restrict__ Wq,
    const float* __restrict__ Wk, const float* __restrict__ Wv,
    const float* __restrict__ Wo,
    __nv_bfloat16* __restrict__ hi, __nv_bfloat16* __restrict__ lo)
{
    long i = (long)blockIdx.x * blockDim.x + threadIdx.x;
    if (i >= 7L * VV * HS) return;
    int mat = (int)(i / ((long)VV * HS));
    long rem = i % ((long)VV * HS);
    int v = (int)(rem / HS);
    int e = (int)(rem % HS);
    float x;
    if (mat < 3) x = mechW[((long)v * NLL + mat) * HS + e];
    else {
        const float* p = (mat == 3) ? Wq : (mat == 4) ? Wk : (mat == 5) ? Wv : Wo;
        x = p[(long)v * HS + e];
    }
    __nv_bfloat16 h = __float2bfloat16(x);
    hi[i] = h;
    lo[i] = __float2bfloat16(x - __bfloat162float(h));
}

// ---------------- kernel 1: causal input z[b,t,i,h] -> bf16 hi/lo -----------
// Asm stored source-major so the big projection loop runs on packed fma2.
__global__ void __launch_bounds__(128) causal_input_kernel(
    const float* __restrict__ x,
    const float* __restrict__ var_emb,
    const float* __restrict__ temp_emb,
    const float* __restrict__ adj,
    __nv_bfloat16* __restrict__ zHi, __nv_bfloat16* __restrict__ zLo)
{
    __shared__ float xlag[VV][12];
    __shared__ float Asm[VV][66];    // [src s][tgt ii], rows 8B-aligned (264B)
    __shared__ float Blsm[LP1][66];  // [lag l][tgt ii]

    int bt = blockIdx.x;
    int b = bt >> 8;
    int t = bt & 255;
    int tid = threadIdx.x;

    for (int i = tid; i < VV * LP1; i += 128) {
        int s = i / LP1, l = i % LP1;
        xlag[s][l] = (t >= l) ? x[(b * SS + (t - l)) * VV + s] : 0.f;
    }
    __syncthreads();

    for (int i = tid; i < VV * VV; i += 128) {
        int s = i >> 6, ii = i & 63;
        const float* ap = adj + (s * VV + ii) * LP1;
        float a = 0.f;
#pragma unroll
        for (int l = 0; l < LP1; l++) a += xlag[s][l] * ap[l];
        Asm[s][ii] = a;
    }
    for (int i = tid; i < VV * LP1; i += 128) {
        int ii = i / LP1, l = i % LP1;
        float a = 0.f;
#pragma unroll 8
        for (int s = 0; s < VV; s++) a += xlag[s][l] * adj[(s * VV + ii) * LP1 + l];
        Blsm[l][ii] = a;
    }
    __syncthreads();

    int h = tid;  // 128 threads == H
    u64 acc2[32];
#pragma unroll
    for (int p = 0; p < 32; p++) acc2[p] = 0ull;
    for (int s = 0; s < VV; s++) {
        float ve = var_emb[s * HH + h];
        u64 ve2 = pack2(ve, ve);
        const u64* arow = (const u64*)&Asm[s][0];
#pragma unroll
        for (int p = 0; p < 32; p++) fma2(acc2[p], arow[p], ve2);
    }
#pragma unroll
    for (int l = 0; l < LP1; l++) {
        float te = temp_emb[l * HH + h];
        u64 te2 = pack2(te, te);
        const u64* brow = (const u64*)&Blsm[l][0];
#pragma unroll
        for (int p = 0; p < 32; p++) fma2(acc2[p], brow[p], te2);
    }
#pragma unroll 8
    for (int p = 0; p < 32; p++) {
        float a0, a1;
        unpack2(acc2[p], a0, a1);
        long o0 = ((long)(2 * p) * BT + bt) * HH + h;
        long o1 = ((long)(2 * p + 1) * BT + bt) * HH + h;
        __nv_bfloat16 h0 = __float2bfloat16(a0);
        __nv_bfloat16 h1 = __float2bfloat16(a1);
        zHi[o0] = h0;
        zLo[o0] = __float2bfloat16(a0 - __bfloat162float(h0));
        zHi[o1] = h1;
        zLo[o1] = __float2bfloat16(a1 - __bfloat162float(h1));
    }
}

// ---------------- kernel 2: per-variable GEMM on tensor cores ---------------
#define A_LD 40
#define B_LD 136
#define E_LD 132
#define ABUF 20480
#define BBUF 17408
#define PV_SMEM_BYTES 75776

template <bool LN_GELU, bool OUT_SPLIT>
__global__ void __launch_bounds__(256, 2) pv_gemm(
    const __nv_bfloat16* __restrict__ Ahi, const __nv_bfloat16* __restrict__ Alo,
    const __nv_bfloat16* __restrict__ Whi, const __nv_bfloat16* __restrict__ Wlo,
    const float* __restrict__ biasB, int bStride,
    const float* __restrict__ gB, const float* __restrict__ betaB,
    float* __restrict__ outF,
    __nv_bfloat16* __restrict__ outHi, __nv_bfloat16* __restrict__ outLo)
{
    extern __shared__ char smem[];
    float* Esm = (float*)smem;

    int v = blockIdx.y;
    int row0 = blockIdx.x * 128;
    const __nv_bfloat16* AhV = Ahi + ((long)v * BT + row0) * HH;
    const __nv_bfloat16* AlV = Alo + ((long)v * BT + row0) * HH;
    const __nv_bfloat16* WhV = Whi + (long)v * HS;
    const __nv_bfloat16* WlV = Wlo + (long)v * HS;
    const float* bias = biasB + (long)v * bStride;

    int tid = threadIdx.x;
    int w = tid >> 5;
    int wr = w >> 2;
    int wc = w & 3;

    unsigned int smem_u32;
    asm("{ .reg .u64 t0; cvta.to.shared.u64 t0, %1; cvt.u32.u64 %0, t0; }"
        : "=r"(smem_u32) : "l"(smem));

    int tA_r = tid >> 2, tA_g = tid & 3;
    int tB_r = tid >> 4, tB_g = tid & 15;
    unsigned int aOff0 = (unsigned int)(tA_r * A_LD + tA_g * 8) * 2u;
    unsigned int aOff1 = (unsigned int)((tA_r + 64) * A_LD + tA_g * 8) * 2u;
    unsigned int bOff0 = (unsigned int)(tB_r * B_LD + tB_g * 8) * 2u;
    unsigned int bOff1 = (unsigned int)((tB_r + 16) * B_LD + tB_g * 8) * 2u;

    auto issue_chunk = [&](int kt, int buf) {
        unsigned int aBase = smem_u32 + buf * ABUF;
        unsigned int bBase = smem_u32 + 2 * ABUF + buf * BBUF;
        const __nv_bfloat16* gah = AhV + (long)tA_r * HH + kt * 32 + tA_g * 8;
        const __nv_bfloat16* gal = AlV + (long)tA_r * HH + kt * 32 + tA_g * 8;
        CPA16(aBase + aOff0, gah);
        CPA16(aBase + aOff1, gah + 64 * HH);
        CPA16(aBase + 10240 + aOff0, gal);
        CPA16(aBase + 10240 + aOff1, gal + 64 * HH);
        const __nv_bfloat16* gwh = WhV + (long)(kt * 32 + tB_r) * HH + tB_g * 8;
        const __nv_bfloat16* gwl = WlV + (long)(kt * 32 + tB_r) * HH + tB_g * 8;
        CPA16(bBase + bOff0, gwh);
        CPA16(bBase + bOff1, gwh + 16 * HH);
        CPA16(bBase + 8704 + bOff0, gwl);
        CPA16(bBase + 8704 + bOff1, gwl + 16 * HH);
        asm volatile("cp.async.commit_group;");
    };

    wmma::fragment<wmma::accumulator, 16, 16, 16, float> acc[4][2];
#pragma unroll
    for (int i = 0; i < 4; i++)
#pragma unroll
        for (int j = 0; j < 2; j++) wmma::fill_fragment(acc[i][j], 0.f);

    issue_chunk(0, 0);
    issue_chunk(1, 1);

#pragma unroll
    for (int kt = 0; kt < 4; kt++) {
        if (kt < 3) { asm volatile("cp.async.wait_group 1;" ::: "memory"); }
        else        { asm volatile("cp.async.wait_group 0;" ::: "memory"); }
        __syncthreads();

        int buf = kt & 1;
        const __nv_bfloat16* Ah = (const __nv_bfloat16*)(smem + buf * ABUF);
        const __nv_bfloat16* Al = (const __nv_bfloat16*)(smem + buf * ABUF + 10240);
        const __nv_bfloat16* Bh = (const __nv_bfloat16*)(smem + 2 * ABUF + buf * BBUF);
        const __nv_bfloat16* Bl = (const __nv_bfloat16*)(smem + 2 * ABUF + buf * BBUF + 8704);

#pragma unroll
        for (int ks = 0; ks < 2; ks++) {
            wmma::fragment<wmma::matrix_a, 16, 16, 16, __nv_bfloat16, wmma::row_major> afh[4], afl[4];
            wmma::fragment<wmma::matrix_b, 16, 16, 16, __nv_bfloat16, wmma::row_major> bfh[2], bfl[2];
#pragma unroll
            for (int i = 0; i < 4; i++) {
                wmma::load_matrix_sync(afh[i], &Ah[(wr * 64 + i * 16) * A_LD + ks * 16], A_LD);
                wmma::load_matrix_sync(afl[i], &Al[(wr * 64 + i * 16) * A_LD + ks * 16], A_LD);
            }
#pragma unroll
            for (int j = 0; j < 2; j++) {
                wmma::load_matrix_sync(bfh[j], &Bh[(ks * 16) * B_LD + wc * 32 + j * 16], B_LD);
                wmma::load_matrix_sync(bfl[j], &Bl[(ks * 16) * B_LD + wc * 32 + j * 16], B_LD);
            }
#pragma unroll
            for (int i = 0; i < 4; i++)
#pragma unroll
                for (int j = 0; j < 2; j++) {
                    wmma::mma_sync(acc[i][j], afh[i], bfh[j], acc[i][j]);
                    wmma::mma_sync(acc[i][j], afh[i], bfl[j], acc[i][j]);
                    wmma::mma_sync(acc[i][j], afl[i], bfh[j], acc[i][j]);
                }
        }
        __syncthreads();
        if (kt < 2) issue_chunk(kt + 2, buf);
    }

#pragma unroll
    for (int i = 0; i < 4; i++)
#pragma unroll
        for (int j = 0; j < 2; j++)
            wmma::store_matrix_sync(&Esm[(wr * 64 + i * 16) * E_LD + wc * 32 + j * 16],
                                    acc[i][j], E_LD, wmma::mem_row_major);
    __syncthreads();

    int row = tid >> 1;
    int ch = (tid & 1) * 64;
    const float* er = Esm + row * E_LD + ch;
    float vals[64];
#pragma unroll
    for (int i = 0; i < 16; i++) {
        float4 x = *(const float4*)&er[i * 4];
        vals[i * 4 + 0] = x.x; vals[i * 4 + 1] = x.y;
        vals[i * 4 + 2] = x.z; vals[i * 4 + 3] = x.w;
    }
#pragma unroll
    for (int i = 0; i < 64; i++) vals[i] += bias[ch + i];

    if (LN_GELU) {
        const float* gp = gB + (long)v * bStride;
        const float* bp = betaB + (long)v * bStride;
        float sum = 0.f, sq = 0.f;
#pragma unroll
        for (int i = 0; i < 64; i++) { sum += vals[i]; sq += vals[i] * vals[i]; }
        sum += __shfl_xor_sync(0xffffffffu, sum, 1);
        sq  += __shfl_xor_sync(0xffffffffu, sq, 1);
        float mu = sum * (1.f / 128.f);
        float var = sq * (1.f / 128.f) - mu * mu;
        float inv = rsqrtf(var + 1e-5f);
#pragma unroll
        for (int i = 0; i < 64; i++) {
            float xn = (vals[i] - mu) * inv * gp[ch + i] + bp[ch + i];
            vals[i] = fast_gelu(xn);
        }
    }

    long rowIdx = ((long)v * BT + row0 + row) * HH + ch;
    if (OUT_SPLIT) {
        __nv_bfloat16 hv[64], lv[64];
#pragma unroll
        for (int i = 0; i < 64; i++) {
            __nv_bfloat16 h = __float2bfloat16(vals[i]);
            hv[i] = h;
            lv[i] = __float2bfloat16(vals[i] - __bfloat162float(h));
        }
#pragma unroll
        for (int g = 0; g < 8; g++) {
            *(uint4*)&outHi[rowIdx + g * 8] = *(uint4*)&hv[g * 8];
            *(uint4*)&outLo[rowIdx + g * 8] = *(uint4*)&lv[g * 8];
        }
    } else {
#pragma unroll
        for (int i = 0; i < 16; i++) {
            float4 s = make_float4(vals[i * 4], vals[i * 4 + 1], vals[i * 4 + 2], vals[i * 4 + 3]);
            *(float4*)&outF[rowIdx + i * 4] = s;
        }
    }
}

// ---------------- kernel 3: attention, packed f32x2, shift-free softmax -----
__global__ void __launch_bounds__(256) attn_kernel(
    const float* __restrict__ q, const float* __restrict__ k,
    const float* __restrict__ vv,
    __nv_bfloat16* __restrict__ oHi, __nv_bfloat16* __restrict__ oLo)
{
    __shared__ ulonglong2 K2[SS * 4];
    __shared__ ulonglong2 V2[SS * 4];

    int g = blockIdx.x;
    int b = g / (VV * NHH);
    int rem = g % (VV * NHH);
    int v = rem / NHH;
    int nh = rem % NHH;

    long base = ((long)v * BT + (long)b * SS) * HH + nh * DHH;
    int t = threadIdx.x;

    const ulonglong2* kp = (const ulonglong2*)(k + base + (long)t * HH);
    const ulonglong2* vp = (const ulonglong2*)(vv + base + (long)t * HH);
#pragma unroll
    for (int d = 0; d < 4; d++) {
        K2[t * 4 + d] = kp[d];
        V2[t * 4 + d] = vp[d];
    }
    const ulonglong2* qp = (const ulonglong2*)(q + base + (long)t * HH);
    u64 q2[8];
#pragma unroll
    for (int d = 0; d < 4; d++) {
        ulonglong2 qa = qp[d];
        q2[d * 2] = qa.x; q2[d * 2 + 1] = qa.y;
    }
    __syncthreads();

    float l = 0.f;
    u64 o2[8];
#pragma unroll
    for (int i = 0; i < 8; i++) o2[i] = 0ull;

#pragma unroll 2
    for (int j = 0; j < SS; j++) {
        ulonglong2 ka = K2[j * 4 + 0], kb2 = K2[j * 4 + 1];
        ulonglong2 kc = K2[j * 4 + 2], kd = K2[j * 4 + 3];
        u64 acc0 = 0ull, acc1 = 0ull;
        fma2(acc0, q2[0], ka.x);  fma2(acc1, q2[1], ka.y);
        fma2(acc0, q2[2], kb2.x); fma2(acc1, q2[3], kb2.y);
        fma2(acc0, q2[4], kc.x);  fma2(acc1, q2[5], kc.y);
        fma2(acc0, q2[6], kd.x);  fma2(acc1, q2[7], kd.y);
        u64 accs = add2(acc0, acc1);
        float slo, shi;
        unpack2(accs, slo, shi);
        float p = __expf((slo + shi) * 0.25f);   // scale = 1/sqrt(16)
        l += p;
        u64 p2 = pack2(p, p);
        ulonglong2 va = V2[j * 4 + 0], vb2 = V2[j * 4 + 1];
        ulonglong2 vc = V2[j * 4 + 2], vd = V2[j * 4 + 3];
        fma2(o2[0], p2, va.x);  fma2(o2[1], p2, va.y);
        fma2(o2[2], p2, vb2.x); fma2(o2[3], p2, vb2.y);
        fma2(o2[4], p2, vc.x);  fma2(o2[5], p2, vc.y);
        fma2(o2[6], p2, vd.x);  fma2(o2[7], p2, vd.y);
    }

    float invl = 1.f / l;
    float of[16];
#pragma unroll
    for (int i = 0; i < 8; i++) {
        float lo, hi;
        unpack2(o2[i], lo, hi);
        of[i * 2] = lo * invl;
        of[i * 2 + 1] = hi * invl;
    }
    __nv_bfloat16 hv[16], lv[16];
#pragma unroll
    for (int i = 0; i < 16; i++) {
        __nv_bfloat16 h = __float2bfloat16(of[i]);
        hv[i] = h;
        lv[i] = __float2bfloat16(of[i] - __bfloat162float(h));
    }
    long obase = base + (long)t * HH;
    *(uint4*)&oHi[obase]     = *(uint4*)&hv[0];
    *(uint4*)&oHi[obase + 8] = *(uint4*)&hv[8];
    *(uint4*)&oLo[obase]     = *(uint4*)&lv[0];
    *(uint4*)&oLo[obase + 8] = *(uint4*)&lv[8];
}

// ---------------- kernel 4: output head predictions[b,t,v] ------------------
__global__ void __launch_bounds__(256) outhead_kernel(
    const float* __restrict__ o2,
    const float* __restrict__ outW, const float* __restrict__ outB,
    float* __restrict__ pred)
{
    int bt = blockIdx.x;
    int tid = threadIdx.x;
    int v = tid >> 2;
    int part = tid & 3;
    const float* row = o2 + ((long)v * BT + bt) * HH + part * 32;
    const float* w = outW + v * HH + part * 32;
    float acc = 0.f;
#pragma unroll 8
    for (int i = 0; i < 32; i++) acc += row[i] * w[i];
    acc += __shfl_xor_sync(0xffffffffu, acc, 1);
    acc += __shfl_xor_sync(0xffffffffu, acc, 2);
    if (part == 0) pred[bt * VV + v] = acc + outB[v];
}

// ---------------- launch ----------------------------------------------------
extern "C" void kernel_launch(void* const* d_in, const int* in_sizes, int n_in,
                              void* d_out, int out_size) {
    const float* x        = (const float*)d_in[0];
    const float* adjl     = (const float*)d_in[1];
    const float* var_emb  = (const float*)d_in[2];
    const float* temp_emb = (const float*)d_in[3];
    const float* mech_W   = (const float*)d_in[4];
    const float* mech_b   = (const float*)d_in[5];
    const float* ln_g     = (const float*)d_in[6];
    const float* ln_b     = (const float*)d_in[7];
    const float* Wq       = (const float*)d_in[8];
    const float* Wk       = (const float*)d_in[9];
    const float* Wv       = (const float*)d_in[10];
    const float* Wo       = (const float*)d_in[11];
    const float* bq       = (const float*)d_in[12];
    const float* bk       = (const float*)d_in[13];
    const float* bv       = (const float*)d_in[14];
    const float* bo       = (const float*)d_in[15];
    const float* out_W    = (const float*)d_in[16];
    const float* out_b    = (const float*)d_in[17];
    float* pred = (float*)d_out;

    float *adj, *qb, *kb, *vb, *z0;
    __nv_bfloat16 *Whi, *Wlo, *zhi0, *zlo0, *zhi1, *zlo1, *ohi, *olo;
    cudaGetSymbolAddress((void**)&adj, g_adj);
    cudaGetSymbolAddress((void**)&Whi, g_Whi);
    cudaGetSymbolAddress((void**)&Wlo, g_Wlo);
    cudaGetSymbolAddress((void**)&zhi0, g_zhi0);
    cudaGetSymbolAddress((void**)&zlo0, g_zlo0);
    cudaGetSymbolAddress((void**)&zhi1, g_zhi1);
    cudaGetSymbolAddress((void**)&zlo1, g_zlo1);
    cudaGetSymbolAddress((void**)&ohi, g_ohi);
    cudaGetSymbolAddress((void**)&olo, g_olo);
    cudaGetSymbolAddress((void**)&qb, g_qb);
    cudaGetSymbolAddress((void**)&kb, g_kb);
    cudaGetSymbolAddress((void**)&vb, g_vb);
    cudaGetSymbolAddress((void**)&z0, g_z0);

    static bool attr_done = false;
    if (!attr_done) {
        cudaFuncSetAttribute((const void*)pv_gemm<true, true>,
                             cudaFuncAttributeMaxDynamicSharedMemorySize, PV_SMEM_BYTES);
        cudaFuncSetAttribute((const void*)pv_gemm<false, false>,
                             cudaFuncAttributeMaxDynamicSharedMemorySize, PV_SMEM_BYTES);
        attr_done = true;
    }

    int nadj = VV * VV * LP1;
    sigmoid_kernel<<<(nadj + 255) / 256, 256>>>(adjl, adj, nadj);

    long nw = 7L * VV * HS;
    split_weights_kernel<<<(int)((nw + 255) / 256), 256>>>(mech_W, Wq, Wk, Wv, Wo, Whi, Wlo);

    causal_input_kernel<<<BT, 128>>>(x, var_emb, temp_emb, adj, zhi0, zlo0);

    dim3 gg(BT / 128, VV);
    const long WSZ = (long)VV * HS;
    pv_gemm<true, true><<<gg, 256, PV_SMEM_BYTES>>>(
        zhi0, zlo0, Whi + 0 * WSZ, Wlo + 0 * WSZ, mech_b + 0 * HH, NLL * HH,
        ln_g + 0 * HH, ln_b + 0 * HH, nullptr, zhi1, zlo1);
    pv_gemm<true, true><<<gg, 256, PV_SMEM_BYTES>>>(
        zhi1, zlo1, Whi + 1 * WSZ, Wlo + 1 * WSZ, mech_b + 1 * HH, NLL * HH,
        ln_g + 1 * HH, ln_b + 1 * HH, nullptr, zhi0, zlo0);
    pv_gemm<true, true><<<gg, 256, PV_SMEM_BYTES>>>(
        zhi0, zlo0, Whi + 2 * WSZ, Wlo + 2 * WSZ, mech_b + 2 * HH, NLL * HH,
        ln_g + 2 * HH, ln_b + 2 * HH, nullptr, zhi1, zlo1);
    pv_gemm<false, false><<<gg, 256, PV_SMEM_BYTES>>>(
        zhi1, zlo1, Whi + 3 * WSZ, Wlo + 3 * WSZ, bq, HH,
        nullptr, nullptr, qb, nullptr, nullptr);
    pv_gemm<false, false><<<gg, 256, PV_SMEM_BYTES>>>(
        zhi1, zlo1, Whi + 4 * WSZ, Wlo + 4 * WSZ, bk, HH,
        nullptr, nullptr, kb, nullptr, nullptr);
    pv_gemm<false, false><<<gg, 256, PV_SMEM_BYTES>>>(
        zhi1, zlo1, Whi + 5 * WSZ, Wlo + 5 * WSZ, bv, HH,
        nullptr, nullptr, vb, nullptr, nullptr);
    attn_kernel<<<BB * VV * NHH, 256>>>(qb, kb, vb, ohi, olo);
    pv_gemm<false, false><<<gg, 256, PV_SMEM_BYTES>>>(
        ohi, olo, Whi + 6 * WSZ, Wlo + 6 * WSZ, bo, HH,
        nullptr, nullptr, z0, nullptr, nullptr);
    outhead_kernel<<<BT, 256>>>(z0, out_W, out_b, pred);
}

// round 15
// speedup vs baseline: 1.5249x; 1.3320x over previous
#include <cuda_runtime.h>
#include <cuda_bf16.h>
#include <mma.h>
#include <math.h>
#include <stdint.h>

using namespace nvcuda;

#define BB 4
#define SS 256
#define VV 64
#define LP1 11
#define HH 128
#define NHH 8
#define DHH 16
#define NLL 3
#define BT 1024   // B*S
#define HS (HH * HH)

typedef unsigned long long u64;

// ---------------- scratch (static device globals; no runtime allocation) ----
__device__ float g_adj[VV * VV * LP1];
__device__ __nv_bfloat16 g_Whi[7L * VV * HS];
__device__ __nv_bfloat16 g_Wlo[7L * VV * HS];
__device__ __nv_bfloat16 g_zhi0[(long)VV * BT * HH];
__device__ __nv_bfloat16 g_zlo0[(long)VV * BT * HH];
__device__ __nv_bfloat16 g_zhi1[(long)VV * BT * HH];
__device__ __nv_bfloat16 g_zlo1[(long)VV * BT * HH];
__device__ __nv_bfloat16 g_ohi[(long)VV * BT * HH];
__device__ __nv_bfloat16 g_olo[(long)VV * BT * HH];
__device__ float g_qb[(long)VV * BT * HH];
__device__ float g_kb[(long)VV * BT * HH];
__device__ float g_vb[(long)VV * BT * HH];
__device__ float g_z0[(long)VV * BT * HH];

// ---------------- packed f32x2 helpers --------------------------------------
__device__ __forceinline__ void fma2(u64& d, u64 a, u64 b) {
    asm("fma.rn.f32x2 %0, %1, %2, %3;" : "=l"(d) : "l"(a), "l"(b), "l"(d));
}
__device__ __forceinline__ u64 pack2(float lo, float hi) {
    u64 r; asm("mov.b64 %0, {%1, %2};" : "=l"(r) : "f"(lo), "f"(hi)); return r;
}
__device__ __forceinline__ void unpack2(u64 v, float& lo, float& hi) {
    asm("mov.b64 {%0, %1}, %2;" : "=f"(lo), "=f"(hi) : "l"(v));
}
__device__ __forceinline__ void split_store2(
    __nv_bfloat16* hi, __nv_bfloat16* lo, int idx, float a, float b)
{
    __nv_bfloat16 ha = __float2bfloat16(a), hb = __float2bfloat16(b);
    __nv_bfloat16 la = __float2bfloat16(a - __bfloat162float(ha));
    __nv_bfloat16 lb = __float2bfloat16(b - __bfloat162float(hb));
    *(__nv_bfloat162*)&hi[idx] = __nv_bfloat162{ha, hb};
    *(__nv_bfloat162*)&lo[idx] = __nv_bfloat162{la, lb};
}
__device__ __forceinline__ float ex2a(float x) {
    float r; asm("ex2.approx.f32 %0, %1;" : "=f"(r) : "f"(x)); return r;
}
// pack two fp32 -> bf16x2 (memory order: lo in low half)
__device__ __forceinline__ uint32_t pkbf2(float lo, float hi) {
    uint32_t r; asm("cvt.rn.bf16x2.f32 %0, %1, %2;" : "=r"(r) : "f"(hi), "f"(lo));
    return r;
}

// ---- fast exact-enough GELU: A&S 7.1.26 erf (|err| <= 1.5e-7 abs) ----------
__device__ __forceinline__ float fast_gelu(float x) {
    float z = fabsf(x) * 0.70710678118654752f;
    float t = __fdividef(1.f, 1.f + 0.3275911f * z);
    float poly = t * (0.254829592f + t * (-0.284496736f +
                 t * (1.421413741f + t * (-1.453152027f + t * 1.061405429f))));
    float erfz = 1.f - poly * __expf(-z * z);
    float erfx = copysignf(erfz, x);
    return 0.5f * x * (1.f + erfx);
}

#define CPA16(smaddr, gptr) \
    asm volatile("cp.async.cg.shared.global [%0], [%1], 16;" :: "r"(smaddr), "l"(gptr))

// ---- raw tensor-core primitives (m16n8k16 bf16, fp32 accum) ----------------
__device__ __forceinline__ void ldsm4(uint32_t* r, uint32_t addr) {
    asm volatile("ldmatrix.sync.aligned.m8n8.x4.shared.b16 {%0,%1,%2,%3}, [%4];"
        : "=r"(r[0]), "=r"(r[1]), "=r"(r[2]), "=r"(r[3]) : "r"(addr));
}
__device__ __forceinline__ void ldsm4t(uint32_t* r, uint32_t addr) {
    asm volatile("ldmatrix.sync.aligned.m8n8.x4.trans.shared.b16 {%0,%1,%2,%3}, [%4];"
        : "=r"(r[0]), "=r"(r[1]), "=r"(r[2]), "=r"(r[3]) : "r"(addr));
}
__device__ __forceinline__ void mma16816(float* d, const uint32_t* a, const uint32_t* b) {
    asm volatile("mma.sync.aligned.m16n8k16.row.col.f32.bf16.bf16.f32 "
        "{%0,%1,%2,%3},{%4,%5,%6,%7},{%8,%9},{%0,%1,%2,%3};"
        : "+f"(d[0]), "+f"(d[1]), "+f"(d[2]), "+f"(d[3])
        : "r"(a[0]), "r"(a[1]), "r"(a[2]), "r"(a[3]), "r"(b[0]), "r"(b[1]));
}

// ---------------- kernel 0: sigmoid of adjacency logits ---------------------
__global__ void sigmoid_kernel(const float* __restrict__ logits, float* __restrict__ adj, int n) {
    int i = blockIdx.x * blockDim.x + threadIdx.x;
    if (i < n) {
        float x = logits[i];
        adj[i] = 1.f / (1.f + __expf(-x));
    }
}

// ---------------- kernel 0b: split all weights to bf16 hi/lo ----------------
__global__ void split_weights_kernel(
    const float* __restrict__ mechW, const float* __restrict__ Wq,
    const float* __restrict__ Wk, const float* __restrict__ Wv,
    const float* __restrict__ Wo,
    __nv_bfloat16* __restrict__ hi, __nv_bfloat16* __restrict__ lo)
{
    long i = (long)blockIdx.x * blockDim.x + threadIdx.x;
    if (i >= 7L * VV * HS) return;
    int mat = (int)(i / ((long)VV * HS));
    long rem = i % ((long)VV * HS);
    int v = (int)(rem / HS);
    int e = (int)(rem % HS);
    float x;
    if (mat < 3) x = mechW[((long)v * NLL + mat) * HS + e];
    else {
        const float* p = (mat == 3) ? Wq : (mat == 4) ? Wk : (mat == 5) ? Wv : Wo;
        x = p[(long)v * HS + e];
    }
    __nv_bfloat16 h = __float2bfloat16(x);
    hi[i] = h;
    lo[i] = __float2bfloat16(x - __bfloat162float(h));
}

// ---------------- kernel 1: causal input z[b,t,i,h] -> bf16 hi/lo -----------
__global__ void __launch_bounds__(128) causal_input_kernel(
    const float* __restrict__ x,
    const float* __restrict__ var_emb,
    const float* __restrict__ temp_emb,
    const float* __restrict__ adj,
    __nv_bfloat16* __restrict__ zHi, __nv_bfloat16* __restrict__ zLo)
{
    __shared__ float xlag[VV][12];
    __shared__ float Asm[VV][66];
    __shared__ float Blsm[LP1][66];

    int bt = blockIdx.x;
    int b = bt >> 8;
    int t = bt & 255;
    int tid = threadIdx.x;

    for (int i = tid; i < VV * LP1; i += 128) {
        int s = i / LP1, l = i % LP1;
        xlag[s][l] = (t >= l) ? x[(b * SS + (t - l)) * VV + s] : 0.f;
    }
    __syncthreads();

    for (int i = tid; i < VV * VV; i += 128) {
        int s = i >> 6, ii = i & 63;
        const float* ap = adj + (s * VV + ii) * LP1;
        float a = 0.f;
#pragma unroll
        for (int l = 0; l < LP1; l++) a += xlag[s][l] * ap[l];
        Asm[s][ii] = a;
    }
    for (int i = tid; i < VV * LP1; i += 128) {
        int ii = i / LP1, l = i % LP1;
        float a = 0.f;
#pragma unroll 8
        for (int s = 0; s < VV; s++) a += xlag[s][l] * adj[(s * VV + ii) * LP1 + l];
        Blsm[l][ii] = a;
    }
    __syncthreads();

    int h = tid;
    u64 acc2[32];
#pragma unroll
    for (int p = 0; p < 32; p++) acc2[p] = 0ull;
    for (int s = 0; s < VV; s++) {
        float ve = var_emb[s * HH + h];
        u64 ve2 = pack2(ve, ve);
        const u64* arow = (const u64*)&Asm[s][0];
#pragma unroll
        for (int p = 0; p < 32; p++) fma2(acc2[p], arow[p], ve2);
    }
#pragma unroll
    for (int l = 0; l < LP1; l++) {
        float te = temp_emb[l * HH + h];
        u64 te2 = pack2(te, te);
        const u64* brow = (const u64*)&Blsm[l][0];
#pragma unroll
        for (int p = 0; p < 32; p++) fma2(acc2[p], brow[p], te2);
    }
#pragma unroll 8
    for (int p = 0; p < 32; p++) {
        float a0, a1;
        unpack2(acc2[p], a0, a1);
        long o0 = ((long)(2 * p) * BT + bt) * HH + h;
        long o1 = ((long)(2 * p + 1) * BT + bt) * HH + h;
        __nv_bfloat16 h0 = __float2bfloat16(a0);
        __nv_bfloat16 h1 = __float2bfloat16(a1);
        zHi[o0] = h0;
        zLo[o0] = __float2bfloat16(a0 - __bfloat162float(h0));
        zHi[o1] = h1;
        zLo[o1] = __float2bfloat16(a1 - __bfloat162float(h1));
    }
}

// ---------------- kernel 2: per-variable GEMM on tensor cores ---------------
#define A_LD 40
#define B_LD 136
#define E_LD 132
#define ABUF 20480
#define BBUF 17408
#define PV_SMEM_BYTES 75776

template <bool LN_GELU, bool OUT_SPLIT>
__global__ void __launch_bounds__(256, 2) pv_gemm(
    const __nv_bfloat16* __restrict__ Ahi, const __nv_bfloat16* __restrict__ Alo,
    const __nv_bfloat16* __restrict__ Whi, const __nv_bfloat16* __restrict__ Wlo,
    const float* __restrict__ biasB, int bStride,
    const float* __restrict__ gB, const float* __restrict__ betaB,
    float* __restrict__ outF,
    __nv_bfloat16* __restrict__ outHi, __nv_bfloat16* __restrict__ outLo)
{
    extern __shared__ char smem[];
    float* Esm = (float*)smem;

    int v = blockIdx.y;
    int row0 = blockIdx.x * 128;
    const __nv_bfloat16* AhV = Ahi + ((long)v * BT + row0) * HH;
    const __nv_bfloat16* AlV = Alo + ((long)v * BT + row0) * HH;
    const __nv_bfloat16* WhV = Whi + (long)v * HS;
    const __nv_bfloat16* WlV = Wlo + (long)v * HS;
    const float* bias = biasB + (long)v * bStride;

    int tid = threadIdx.x;
    int w = tid >> 5;
    int wr = w >> 2;
    int wc = w & 3;

    unsigned int smem_u32;
    asm("{ .reg .u64 t0; cvta.to.shared.u64 t0, %1; cvt.u32.u64 %0, t0; }"
        : "=r"(smem_u32) : "l"(smem));

    int tA_r = tid >> 2, tA_g = tid & 3;
    int tB_r = tid >> 4, tB_g = tid & 15;
    unsigned int aOff0 = (unsigned int)(tA_r * A_LD + tA_g * 8) * 2u;
    unsigned int aOff1 = (unsigned int)((tA_r + 64) * A_LD + tA_g * 8) * 2u;
    unsigned int bOff0 = (unsigned int)(tB_r * B_LD + tB_g * 8) * 2u;
    unsigned int bOff1 = (unsigned int)((tB_r + 16) * B_LD + tB_g * 8) * 2u;

    auto issue_chunk = [&](int kt, int buf) {
        unsigned int aBase = smem_u32 + buf * ABUF;
        unsigned int bBase = smem_u32 + 2 * ABUF + buf * BBUF;
        const __nv_bfloat16* gah = AhV + (long)tA_r * HH + kt * 32 + tA_g * 8;
        const __nv_bfloat16* gal = AlV + (long)tA_r * HH + kt * 32 + tA_g * 8;
        CPA16(aBase + aOff0, gah);
        CPA16(aBase + aOff1, gah + 64 * HH);
        CPA16(aBase + 10240 + aOff0, gal);
        CPA16(aBase + 10240 + aOff1, gal + 64 * HH);
        const __nv_bfloat16* gwh = WhV + (long)(kt * 32 + tB_r) * HH + tB_g * 8;
        const __nv_bfloat16* gwl = WlV + (long)(kt * 32 + tB_r) * HH + tB_g * 8;
        CPA16(bBase + bOff0, gwh);
        CPA16(bBase + bOff1, gwh + 16 * HH);
        CPA16(bBase + 8704 + bOff0, gwl);
        CPA16(bBase + 8704 + bOff1, gwl + 16 * HH);
        asm volatile("cp.async.commit_group;");
    };

    wmma::fragment<wmma::accumulator, 16, 16, 16, float> acc[4][2];
#pragma unroll
    for (int i = 0; i < 4; i++)
#pragma unroll
        for (int j = 0; j < 2; j++) wmma::fill_fragment(acc[i][j], 0.f);

    issue_chunk(0, 0);
    issue_chunk(1, 1);

#pragma unroll
    for (int kt = 0; kt < 4; kt++) {
        if (kt < 3) { asm volatile("cp.async.wait_group 1;" ::: "memory"); }
        else        { asm volatile("cp.async.wait_group 0;" ::: "memory"); }
        __syncthreads();

        int buf = kt & 1;
        const __nv_bfloat16* Ah = (const __nv_bfloat16*)(smem + buf * ABUF);
        const __nv_bfloat16* Al = (const __nv_bfloat16*)(smem + buf * ABUF + 10240);
        const __nv_bfloat16* Bh = (const __nv_bfloat16*)(smem + 2 * ABUF + buf * BBUF);
        const __nv_bfloat16* Bl = (const __nv_bfloat16*)(smem + 2 * ABUF + buf * BBUF + 8704);

#pragma unroll
        for (int ks = 0; ks < 2; ks++) {
            wmma::fragment<wmma::matrix_a, 16, 16, 16, __nv_bfloat16, wmma::row_major> afh[4], afl[4];
            wmma::fragment<wmma::matrix_b, 16, 16, 16, __nv_bfloat16, wmma::row_major> bfh[2], bfl[2];
#pragma unroll
            for (int i = 0; i < 4; i++) {
                wmma::load_matrix_sync(afh[i], &Ah[(wr * 64 + i * 16) * A_LD + ks * 16], A_LD);
                wmma::load_matrix_sync(afl[i], &Al[(wr * 64 + i * 16) * A_LD + ks * 16], A_LD);
            }
#pragma unroll
            for (int j = 0; j < 2; j++) {
                wmma::load_matrix_sync(bfh[j], &Bh[(ks * 16) * B_LD + wc * 32 + j * 16], B_LD);
                wmma::load_matrix_sync(bfl[j], &Bl[(ks * 16) * B_LD + wc * 32 + j * 16], B_LD);
            }
#pragma unroll
            for (int i = 0; i < 4; i++)
#pragma unroll
                for (int j = 0; j < 2; j++) {
                    wmma::mma_sync(acc[i][j], afh[i], bfh[j], acc[i][j]);
                    wmma::mma_sync(acc[i][j], afh[i], bfl[j], acc[i][j]);
                    wmma::mma_sync(acc[i][j], afl[i], bfh[j], acc[i][j]);
                }
        }
        __syncthreads();
        if (kt < 2) issue_chunk(kt + 2, buf);
    }

#pragma unroll
    for (int i = 0; i < 4; i++)
#pragma unroll
        for (int j = 0; j < 2; j++)
            wmma::store_matrix_sync(&Esm[(wr * 64 + i * 16) * E_LD + wc * 32 + j * 16],
                                    acc[i][j], E_LD, wmma::mem_row_major);
    __syncthreads();

    int row = tid >> 1;
    int ch = (tid & 1) * 64;
    const float* er = Esm + row * E_LD + ch;
    float vals[64];
#pragma unroll
    for (int i = 0; i < 16; i++) {
        float4 x = *(const float4*)&er[i * 4];
        vals[i * 4 + 0] = x.x; vals[i * 4 + 1] = x.y;
        vals[i * 4 + 2] = x.z; vals[i * 4 + 3] = x.w;
    }
#pragma unroll
    for (int i = 0; i < 64; i++) vals[i] += bias[ch + i];

    if (LN_GELU) {
        const float* gp = gB + (long)v * bStride;
        const float* bp = betaB + (long)v * bStride;
        float sum = 0.f, sq = 0.f;
#pragma unroll
        for (int i = 0; i < 64; i++) { sum += vals[i]; sq += vals[i] * vals[i]; }
        sum += __shfl_xor_sync(0xffffffffu, sum, 1);
        sq  += __shfl_xor_sync(0xffffffffu, sq, 1);
        float mu = sum * (1.f / 128.f);
        float var = sq * (1.f / 128.f) - mu * mu;
        float inv = rsqrtf(var + 1e-5f);
#pragma unroll
        for (int i = 0; i < 64; i++) {
            float xn = (vals[i] - mu) * inv * gp[ch + i] + bp[ch + i];
            vals[i] = fast_gelu(xn);
        }
    }

    long rowIdx = ((long)v * BT + row0 + row) * HH + ch;
    if (OUT_SPLIT) {
        __nv_bfloat16 hv[64], lv[64];
#pragma unroll
        for (int i = 0; i < 64; i++) {
            __nv_bfloat16 h = __float2bfloat16(vals[i]);
            hv[i] = h;
            lv[i] = __float2bfloat16(vals[i] - __bfloat162float(h));
        }
#pragma unroll
        for (int g = 0; g < 8; g++) {
            *(uint4*)&outHi[rowIdx + g * 8] = *(uint4*)&hv[g * 8];
            *(uint4*)&outLo[rowIdx + g * 8] = *(uint4*)&lv[g * 8];
        }
    } else {
#pragma unroll
        for (int i = 0; i < 16; i++) {
            float4 s = make_float4(vals[i * 4], vals[i * 4 + 1], vals[i * 4 + 2], vals[i * 4 + 3]);
            *(float4*)&outF[rowIdx + i * 4] = s;
        }
    }
}

// ---------------- kernel 3: flash-style mma attention per (b,v,head) --------
// Raw m16n8k16 bf16 MMAs, split hi/lo 3-product compensation, P in registers.
// smem: Q/K/V hi+lo, each [256][24] bf16 (48B rows): 6 * 12288 = 73728 bytes.
#define ALD 24
#define ATTN_SMEM 73728

__global__ void __launch_bounds__(256, 2) attn_mma_kernel(
    const float* __restrict__ q, const float* __restrict__ k,
    const float* __restrict__ vv,
    __nv_bfloat16* __restrict__ oHi, __nv_bfloat16* __restrict__ oLo)
{
    extern __shared__ char sm[];
    __nv_bfloat16* Qh = (__nv_bfloat16*)(sm);
    __nv_bfloat16* Ql = (__nv_bfloat16*)(sm + 12288);
    __nv_bfloat16* Kh = (__nv_bfloat16*)(sm + 24576);
    __nv_bfloat16* Kl = (__nv_bfloat16*)(sm + 36864);
    __nv_bfloat16* Vh = (__nv_bfloat16*)(sm + 49152);
    __nv_bfloat16* Vl = (__nv_bfloat16*)(sm + 61440);

    int g = blockIdx.x;
    int b = g / (VV * NHH);
    int rem = g % (VV * NHH);
    int v = rem / NHH;
    int nh = rem % NHH;
    long base = ((long)v * BT + (long)b * SS) * HH + nh * DHH;

    int tid = threadIdx.x;
    int w = tid >> 5;
    int lane = tid & 31;

    // ---- stage + split Q,K,V (one row per thread) ----
    {
        int r = tid;
        const float* qp = q + base + (long)r * HH;
        const float* kp = k + base + (long)r * HH;
        const float* vp = vv + base + (long)r * HH;
#pragma unroll
        for (int i = 0; i < 4; i++) {
            float4 xq = *(const float4*)(qp + i * 4);
            float4 xk = *(const float4*)(kp + i * 4);
            float4 xv = *(const float4*)(vp + i * 4);
            split_store2(Qh, Ql, r * ALD + i * 4,     xq.x, xq.y);
            split_store2(Qh, Ql, r * ALD + i * 4 + 2, xq.z, xq.w);
            split_store2(Kh, Kl, r * ALD + i * 4,     xk.x, xk.y);
            split_store2(Kh, Kl, r * ALD + i * 4 + 2, xk.z, xk.w);
            split_store2(Vh, Vl, r * ALD + i * 4,     xv.x, xv.y);
            split_store2(Vh, Vl, r * ALD + i * 4 + 2, xv.z, xv.w);
        }
    }
    __syncthreads();

    unsigned int smem_u32;
    asm("{ .reg .u64 t0; cvta.to.shared.u64 t0, %1; cvt.u32.u64 %0, t0; }"
        : "=r"(smem_u32) : "l"(sm));

    // per-lane ldmatrix source rows/cols
    int qr = (lane & 7) + ((lane & 8) ? 8 : 0);
    int qc = (lane & 16) ? 8 : 0;                 // A-operand (Q): m16x16
    int kr = (lane & 7) + ((lane & 16) ? 8 : 0);
    int kc = (lane & 8) ? 8 : 0;                  // B-operand (K, non-trans)
    int vr = (lane & 7) + ((lane & 8) ? 8 : 0);
    int vc = (lane & 16) ? 8 : 0;                 // B-operand (V, trans)

    // persistent Q fragments: row tiles w*32, w*32+16
    uint32_t qfh[2][4], qfl[2][4];
#pragma unroll
    for (int i = 0; i < 2; i++) {
        unsigned int off = (unsigned int)(((w * 32 + i * 16 + qr) * ALD + qc) * 2);
        ldsm4(qfh[i], smem_u32 + 0     + off);
        ldsm4(qfl[i], smem_u32 + 12288 + off);
    }

    float oacc[2][2][4];   // [row tile][dim tile][frag]
#pragma unroll
    for (int i = 0; i < 2; i++)
#pragma unroll
        for (int n = 0; n < 2; n++)
#pragma unroll
            for (int e = 0; e < 4; e++) oacc[i][n][e] = 0.f;
    float lsum[4] = {0.f, 0.f, 0.f, 0.f};   // [row tile*2 + row half]

    const float c0 = 0.25f * 1.4426950408889634f;  // scale * log2(e)

    for (int kt = 0; kt < 16; kt++) {
        // K,V fragments for keys kt*16..+15 (hi and lo)
        uint32_t kh4[4], kl4[4], vh4[4], vl4[4];
        {
            unsigned int koff = (unsigned int)(((kt * 16 + kr) * ALD + kc) * 2);
            unsigned int voff = (unsigned int)(((kt * 16 + vr) * ALD + vc) * 2);
            ldsm4 (kh4, smem_u32 + 24576 + koff);
            ldsm4 (kl4, smem_u32 + 36864 + koff);
            ldsm4t(vh4, smem_u32 + 49152 + voff);
            ldsm4t(vl4, smem_u32 + 61440 + voff);
        }

#pragma unroll
        for (int i = 0; i < 2; i++) {
            // scores: rows (w*32+i*16..+15) x 16 keys, 3-product compensation
            float s0[4] = {0.f, 0.f, 0.f, 0.f};   // keys 0-7 of tile
            float s1[4] = {0.f, 0.f, 0.f, 0.f};   // keys 8-15
            mma16816(s0, qfh[i], &kh4[0]);
            mma16816(s0, qfh[i], &kl4[0]);
            mma16816(s0, qfl[i], &kh4[0]);
            mma16816(s1, qfh[i], &kh4[2]);
            mma16816(s1, qfh[i], &kl4[2]);
            mma16816(s1, qfl[i], &kh4[2]);

            // exp (shift-free; scores are O(few))
            float p00 = ex2a(s0[0] * c0), p01 = ex2a(s0[1] * c0);
            float p02 = ex2a(s0[2] * c0), p03 = ex2a(s0[3] * c0);
            float p10 = ex2a(s1[0] * c0), p11 = ex2a(s1[1] * c0);
            float p12 = ex2a(s1[2] * c0), p13 = ex2a(s1[3] * c0);

            lsum[i * 2 + 0] += (p00 + p01) + (p10 + p11);
            lsum[i * 2 + 1] += (p02 + p03) + (p12 + p13);

            // P -> A fragment (C layout == A layout), split hi/lo in-register
            uint32_t ph[4], pl[4];
            ph[0] = pkbf2(p00, p01); ph[1] = pkbf2(p02, p03);
            ph[2] = pkbf2(p10, p11); ph[3] = pkbf2(p12, p13);
            {
                float h0 = __uint_as_float(ph[0] << 16);
                float h1 = __uint_as_float(ph[0] & 0xffff0000u);
                pl[0] = pkbf2(p00 - h0, p01 - h1);
                h0 = __uint_as_float(ph[1] << 16);
                h1 = __uint_as_float(ph[1] & 0xffff0000u);
                pl[1] = pkbf2(p02 - h0, p03 - h1);
                h0 = __uint_as_float(ph[2] << 16);
                h1 = __uint_as_float(ph[2] & 0xffff0000u);
                pl[2] = pkbf2(p10 - h0, p11 - h1);
                h0 = __uint_as_float(ph[3] << 16);
                h1 = __uint_as_float(ph[3] & 0xffff0000u);
                pl[3] = pkbf2(p12 - h0, p13 - h1);
            }

            // O += P @ V  (dims tiles n=0,1)
#pragma unroll
            for (int n = 0; n < 2; n++) {
                mma16816(oacc[i][n], ph, &vh4[n * 2]);
                mma16816(oacc[i][n], ph, &vl4[n * 2]);
                mma16816(oacc[i][n], pl, &vh4[n * 2]);
            }
        }
    }

    // ---- row-sum reduce (4 threads per row share groupID) ----
#pragma unroll
    for (int j = 0; j < 4; j++) {
        lsum[j] += __shfl_xor_sync(0xffffffffu, lsum[j], 1);
        lsum[j] += __shfl_xor_sync(0xffffffffu, lsum[j], 2);
    }
    float inv[4];
#pragma unroll
    for (int j = 0; j < 4; j++) inv[j] = 1.f / lsum[j];

    // ---- normalize + split-bf16 store ----
    int g2 = lane >> 2, tq = lane & 3;
#pragma unroll
    for (int i = 0; i < 2; i++) {
#pragma unroll
        for (int n = 0; n < 2; n++) {
            float o0 = oacc[i][n][0] * inv[i * 2 + 0];
            float o1 = oacc[i][n][1] * inv[i * 2 + 0];
            float o2 = oacc[i][n][2] * inv[i * 2 + 1];
            float o3 = oacc[i][n][3] * inv[i * 2 + 1];
            int rowA = w * 32 + i * 16 + g2;
            int col = n * 8 + tq * 2;
            long obA = base + (long)rowA * HH + col;
            long obB = obA + 8L * HH;
            uint32_t hA = pkbf2(o0, o1);
            uint32_t hB = pkbf2(o2, o3);
            float hA0 = __uint_as_float(hA << 16), hA1 = __uint_as_float(hA & 0xffff0000u);
            float hB0 = __uint_as_float(hB << 16), hB1 = __uint_as_float(hB & 0xffff0000u);
            *(uint32_t*)&oHi[obA] = hA;
            *(uint32_t*)&oHi[obB] = hB;
            *(uint32_t*)&oLo[obA] = pkbf2(o0 - hA0, o1 - hA1);
            *(uint32_t*)&oLo[obB] = pkbf2(o2 - hB0, o3 - hB1);
        }
    }
}

// ---------------- kernel 4: output head predictions[b,t,v] ------------------
__global__ void __launch_bounds__(256) outhead_kernel(
    const float* __restrict__ o2,
    const float* __restrict__ outW, const float* __restrict__ outB,
    float* __restrict__ pred)
{
    int bt = blockIdx.x;
    int tid = threadIdx.x;
    int v = tid >> 2;
    int part = tid & 3;
    const float* row = o2 + ((long)v * BT + bt) * HH + part * 32;
    const float* w = outW + v * HH + part * 32;
    float acc = 0.f;
#pragma unroll 8
    for (int i = 0; i < 32; i++) acc += row[i] * w[i];
    acc += __shfl_xor_sync(0xffffffffu, acc, 1);
    acc += __shfl_xor_sync(0xffffffffu, acc, 2);
    if (part == 0) pred[bt * VV + v] = acc + outB[v];
}

// ---------------- launch ----------------------------------------------------
extern "C" void kernel_launch(void* const* d_in, const int* in_sizes, int n_in,
                              void* d_out, int out_size) {
    const float* x        = (const float*)d_in[0];
    const float* adjl     = (const float*)d_in[1];
    const float* var_emb  = (const float*)d_in[2];
    const float* temp_emb = (const float*)d_in[3];
    const float* mech_W   = (const float*)d_in[4];
    const float* mech_b   = (const float*)d_in[5];
    const float* ln_g     = (const float*)d_in[6];
    const float* ln_b     = (const float*)d_in[7];
    const float* Wq       = (const float*)d_in[8];
    const float* Wk       = (const float*)d_in[9];
    const float* Wv       = (const float*)d_in[10];
    const float* Wo       = (const float*)d_in[11];
    const float* bq       = (const float*)d_in[12];
    const float* bk       = (const float*)d_in[13];
    const float* bv       = (const float*)d_in[14];
    const float* bo       = (const float*)d_in[15];
    const float* out_W    = (const float*)d_in[16];
    const float* out_b    = (const float*)d_in[17];
    float* pred = (float*)d_out;

    float *adj, *qb, *kb, *vb, *z0;
    __nv_bfloat16 *Whi, *Wlo, *zhi0, *zlo0, *zhi1, *zlo1, *ohi, *olo;
    cudaGetSymbolAddress((void**)&adj, g_adj);
    cudaGetSymbolAddress((void**)&Whi, g_Whi);
    cudaGetSymbolAddress((void**)&Wlo, g_Wlo);
    cudaGetSymbolAddress((void**)&zhi0, g_zhi0);
    cudaGetSymbolAddress((void**)&zlo0, g_zlo0);
    cudaGetSymbolAddress((void**)&zhi1, g_zhi1);
    cudaGetSymbolAddress((void**)&zlo1, g_zlo1);
    cudaGetSymbolAddress((void**)&ohi, g_ohi);
    cudaGetSymbolAddress((void**)&olo, g_olo);
    cudaGetSymbolAddress((void**)&qb, g_qb);
    cudaGetSymbolAddress((void**)&kb, g_kb);
    cudaGetSymbolAddress((void**)&vb, g_vb);
    cudaGetSymbolAddress((void**)&z0, g_z0);

    static bool attr_done = false;
    if (!attr_done) {
        cudaFuncSetAttribute((const void*)pv_gemm<true, true>,
                             cudaFuncAttributeMaxDynamicSharedMemorySize, PV_SMEM_BYTES);
        cudaFuncSetAttribute((const void*)pv_gemm<false, false>,
                             cudaFuncAttributeMaxDynamicSharedMemorySize, PV_SMEM_BYTES);
        cudaFuncSetAttribute((const void*)attn_mma_kernel,
                             cudaFuncAttributeMaxDynamicSharedMemorySize, ATTN_SMEM);
        attr_done = true;
    }

    int nadj = VV * VV * LP1;
    sigmoid_kernel<<<(nadj + 255) / 256, 256>>>(adjl, adj, nadj);

    long nw = 7L * VV * HS;
    split_weights_kernel<<<(int)((nw + 255) / 256), 256>>>(mech_W, Wq, Wk, Wv, Wo, Whi, Wlo);

    causal_input_kernel<<<BT, 128>>>(x, var_emb, temp_emb, adj, zhi0, zlo0);

    dim3 gg(BT / 128, VV);
    const long WSZ = (long)VV * HS;
    pv_gemm<true, true><<<gg, 256, PV_SMEM_BYTES>>>(
        zhi0, zlo0, Whi + 0 * WSZ, Wlo + 0 * WSZ, mech_b + 0 * HH, NLL * HH,
        ln_g + 0 * HH, ln_b + 0 * HH, nullptr, zhi1, zlo1);
    pv_gemm<true, true><<<gg, 256, PV_SMEM_BYTES>>>(
        zhi1, zlo1, Whi + 1 * WSZ, Wlo + 1 * WSZ, mech_b + 1 * HH, NLL * HH,
        ln_g + 1 * HH, ln_b + 1 * HH, nullptr, zhi0, zlo0);
    pv_gemm<true, true><<<gg, 256, PV_SMEM_BYTES>>>(
        zhi0, zlo0, Whi + 2 * WSZ, Wlo + 2 * WSZ, mech_b + 2 * HH, NLL * HH,
        ln_g + 2 * HH, ln_b + 2 * HH, nullptr, zhi1, zlo1);
    pv_gemm<false, false><<<gg, 256, PV_SMEM_BYTES>>>(
        zhi1, zlo1, Whi + 3 * WSZ, Wlo + 3 * WSZ, bq, HH,
        nullptr, nullptr, qb, nullptr, nullptr);
    pv_gemm<false, false><<<gg, 256, PV_SMEM_BYTES>>>(
        zhi1, zlo1, Whi + 4 * WSZ, Wlo + 4 * WSZ, bk, HH,
        nullptr, nullptr, kb, nullptr, nullptr);
    pv_gemm<false, false><<<gg, 256, PV_SMEM_BYTES>>>(
        zhi1, zlo1, Whi + 5 * WSZ, Wlo + 5 * WSZ, bv, HH,
        nullptr, nullptr, vb, nullptr, nullptr);
    attn_mma_kernel<<<BB * VV * NHH, 256, ATTN_SMEM>>>(qb, kb, vb, ohi, olo);
    pv_gemm<false, false><<<gg, 256, PV_SMEM_BYTES>>>(
        ohi, olo, Whi + 6 * WSZ, Wlo + 6 * WSZ, bo, HH,
        nullptr, nullptr, z0, nullptr, nullptr);
    outhead_kernel<<<BT, 256>>>(z0, out_W, out_b, pred);
}

// round 16
// speedup vs baseline: 1.5523x; 1.0180x over previous
#include <cuda_runtime.h>
#include <cuda_bf16.h>
#include <mma.h>
#include <math.h>
#include <stdint.h>

using namespace nvcuda;

#define BB 4
#define SS 256
#define VV 64
#define LP1 11
#define HH 128
#define NHH 8
#define DHH 16
#define NLL 3
#define BT 1024   // B*S
#define HS (HH * HH)

typedef unsigned long long u64;

// ---------------- scratch (static device globals; no runtime allocation) ----
__device__ float g_adj[VV * VV * LP1];
__device__ __nv_bfloat16 g_Whi[7L * VV * HS];
__device__ __nv_bfloat16 g_Wlo[7L * VV * HS];
__device__ __nv_bfloat16 g_zhi0[(long)VV * BT * HH];
__device__ __nv_bfloat16 g_zlo0[(long)VV * BT * HH];
__device__ __nv_bfloat16 g_zhi1[(long)VV * BT * HH];
__device__ __nv_bfloat16 g_zlo1[(long)VV * BT * HH];
__device__ __nv_bfloat16 g_ohi[(long)VV * BT * HH];
__device__ __nv_bfloat16 g_olo[(long)VV * BT * HH];
__device__ __nv_bfloat16 g_qhi[(long)VV * BT * HH];
__device__ __nv_bfloat16 g_qlo[(long)VV * BT * HH];
__device__ __nv_bfloat16 g_khi[(long)VV * BT * HH];
__device__ __nv_bfloat16 g_klo[(long)VV * BT * HH];
__device__ __nv_bfloat16 g_vhi[(long)VV * BT * HH];
__device__ __nv_bfloat16 g_vlo[(long)VV * BT * HH];
__device__ float g_z0[(long)VV * BT * HH];

// ---------------- packed helpers --------------------------------------------
__device__ __forceinline__ void fma2(u64& d, u64 a, u64 b) {
    asm("fma.rn.f32x2 %0, %1, %2, %3;" : "=l"(d) : "l"(a), "l"(b), "l"(d));
}
__device__ __forceinline__ u64 pack2(float lo, float hi) {
    u64 r; asm("mov.b64 %0, {%1, %2};" : "=l"(r) : "f"(lo), "f"(hi)); return r;
}
__device__ __forceinline__ void unpack2(u64 v, float& lo, float& hi) {
    asm("mov.b64 {%0, %1}, %2;" : "=f"(lo), "=f"(hi) : "l"(v));
}
__device__ __forceinline__ float ex2a(float x) {
    float r; asm("ex2.approx.f32 %0, %1;" : "=f"(r) : "f"(x)); return r;
}
// pack two fp32 -> bf16x2 (memory order: first arg in low half)
__device__ __forceinline__ uint32_t pkbf2(float lo, float hi) {
    uint32_t r; asm("cvt.rn.bf16x2.f32 %0, %1, %2;" : "=r"(r) : "f"(hi), "f"(lo));
    return r;
}
__device__ __forceinline__ void split_store2(
    __nv_bfloat16* hi, __nv_bfloat16* lo, int idx, float a, float b)
{
    uint32_t h2 = pkbf2(a, b);
    float h0 = __uint_as_float(h2 << 16);
    float h1 = __uint_as_float(h2 & 0xffff0000u);
    *(uint32_t*)&hi[idx] = h2;
    *(uint32_t*)&lo[idx] = pkbf2(a - h0, b - h1);
}

// ---- fast exact-enough GELU: A&S 7.1.26 erf (|err| <= 1.5e-7 abs) ----------
__device__ __forceinline__ float fast_gelu(float x) {
    float z = fabsf(x) * 0.70710678118654752f;
    float t = __fdividef(1.f, 1.f + 0.3275911f * z);
    float poly = t * (0.254829592f + t * (-0.284496736f +
                 t * (1.421413741f + t * (-1.453152027f + t * 1.061405429f))));
    float erfz = 1.f - poly * __expf(-z * z);
    float erfx = copysignf(erfz, x);
    return 0.5f * x * (1.f + erfx);
}

#define CPA16(smaddr, gptr) \
    asm volatile("cp.async.cg.shared.global [%0], [%1], 16;" :: "r"(smaddr), "l"(gptr))

// ---- raw tensor-core primitives (m16n8k16 bf16, fp32 accum) ----------------
__device__ __forceinline__ void ldsm4(uint32_t* r, uint32_t addr) {
    asm volatile("ldmatrix.sync.aligned.m8n8.x4.shared.b16 {%0,%1,%2,%3}, [%4];"
        : "=r"(r[0]), "=r"(r[1]), "=r"(r[2]), "=r"(r[3]) : "r"(addr));
}
__device__ __forceinline__ void ldsm4t(uint32_t* r, uint32_t addr) {
    asm volatile("ldmatrix.sync.aligned.m8n8.x4.trans.shared.b16 {%0,%1,%2,%3}, [%4];"
        : "=r"(r[0]), "=r"(r[1]), "=r"(r[2]), "=r"(r[3]) : "r"(addr));
}
__device__ __forceinline__ void mma16816(float* d, const uint32_t* a, const uint32_t* b) {
    asm volatile("mma.sync.aligned.m16n8k16.row.col.f32.bf16.bf16.f32 "
        "{%0,%1,%2,%3},{%4,%5,%6,%7},{%8,%9},{%0,%1,%2,%3};"
        : "+f"(d[0]), "+f"(d[1]), "+f"(d[2]), "+f"(d[3])
        : "r"(a[0]), "r"(a[1]), "r"(a[2]), "r"(a[3]), "r"(b[0]), "r"(b[1]));
}

// ---------------- kernel 0: sigmoid of adjacency logits ---------------------
__global__ void sigmoid_kernel(const float* __restrict__ logits, float* __restrict__ adj, int n) {
    int i = blockIdx.x * blockDim.x + threadIdx.x;
    if (i < n) {
        float x = logits[i];
        adj[i] = 1.f / (1.f + __expf(-x));
    }
}

// ---------------- kernel 0b: split all weights to bf16 hi/lo ----------------
__global__ void split_weights_kernel(
    const float* __restrict__ mechW, const float* __restrict__ Wq,
    const float* __restrict__ Wk, const float* __restrict__ Wv,
    const float* __restrict__ Wo,
    __nv_bfloat16* __restrict__ hi, __nv_bfloat16* __restrict__ lo)
{
    long i = (long)blockIdx.x * blockDim.x + threadIdx.x;
    if (i >= 7L * VV * HS) return;
    int mat = (int)(i / ((long)VV * HS));
    long rem = i % ((long)VV * HS);
    int v = (int)(rem / HS);
    int e = (int)(rem % HS);
    float x;
    if (mat < 3) x = mechW[((long)v * NLL + mat) * HS + e];
    else {
        const float* p = (mat == 3) ? Wq : (mat == 4) ? Wk : (mat == 5) ? Wv : Wo;
        x = p[(long)v * HS + e];
    }
    __nv_bfloat16 h = __float2bfloat16(x);
    hi[i] = h;
    lo[i] = __float2bfloat16(x - __bfloat162float(h));
}

// ---------------- kernel 1: causal input z[b,t,i,h] -> bf16 hi/lo -----------
__global__ void __launch_bounds__(128) causal_input_kernel(
    const float* __restrict__ x,
    const float* __restrict__ var_emb,
    const float* __restrict__ temp_emb,
    const float* __restrict__ adj,
    __nv_bfloat16* __restrict__ zHi, __nv_bfloat16* __restrict__ zLo)
{
    __shared__ float xlag[VV][12];
    __shared__ float Asm[VV][66];
    __shared__ float Blsm[LP1][66];

    int bt = blockIdx.x;
    int b = bt >> 8;
    int t = bt & 255;
    int tid = threadIdx.x;

    for (int i = tid; i < VV * LP1; i += 128) {
        int s = i / LP1, l = i % LP1;
        xlag[s][l] = (t >= l) ? x[(b * SS + (t - l)) * VV + s] : 0.f;
    }
    __syncthreads();

    for (int i = tid; i < VV * VV; i += 128) {
        int s = i >> 6, ii = i & 63;
        const float* ap = adj + (s * VV + ii) * LP1;
        float a = 0.f;
#pragma unroll
        for (int l = 0; l < LP1; l++) a += xlag[s][l] * ap[l];
        Asm[s][ii] = a;
    }
    for (int i = tid; i < VV * LP1; i += 128) {
        int ii = i / LP1, l = i % LP1;
        float a = 0.f;
#pragma unroll 8
        for (int s = 0; s < VV; s++) a += xlag[s][l] * adj[(s * VV + ii) * LP1 + l];
        Blsm[l][ii] = a;
    }
    __syncthreads();

    int h = tid;
    u64 acc2[32];
#pragma unroll
    for (int p = 0; p < 32; p++) acc2[p] = 0ull;
    for (int s = 0; s < VV; s++) {
        float ve = var_emb[s * HH + h];
        u64 ve2 = pack2(ve, ve);
        const u64* arow = (const u64*)&Asm[s][0];
#pragma unroll
        for (int p = 0; p < 32; p++) fma2(acc2[p], arow[p], ve2);
    }
#pragma unroll
    for (int l = 0; l < LP1; l++) {
        float te = temp_emb[l * HH + h];
        u64 te2 = pack2(te, te);
        const u64* brow = (const u64*)&Blsm[l][0];
#pragma unroll
        for (int p = 0; p < 32; p++) fma2(acc2[p], brow[p], te2);
    }
#pragma unroll 8
    for (int p = 0; p < 32; p++) {
        float a0, a1;
        unpack2(acc2[p], a0, a1);
        long o0 = ((long)(2 * p) * BT + bt) * HH + h;
        long o1 = ((long)(2 * p + 1) * BT + bt) * HH + h;
        __nv_bfloat16 h0 = __float2bfloat16(a0);
        __nv_bfloat16 h1 = __float2bfloat16(a1);
        zHi[o0] = h0;
        zLo[o0] = __float2bfloat16(a0 - __bfloat162float(h0));
        zHi[o1] = h1;
        zLo[o1] = __float2bfloat16(a1 - __bfloat162float(h1));
    }
}

// ---------------- pv_gemm core: 128x128x128 split-bf16 tile -> Esm ----------
#define A_LD 40
#define B_LD 136
#define E_LD 132
#define ABUF 20480
#define BBUF 17408
#define PV_SMEM_BYTES 75776

__device__ __forceinline__ void pv_core(
    const __nv_bfloat16* __restrict__ AhV, const __nv_bfloat16* __restrict__ AlV,
    const __nv_bfloat16* __restrict__ WhV, const __nv_bfloat16* __restrict__ WlV,
    char* smem, int tid)
{
    float* Esm = (float*)smem;
    int w = tid >> 5;
    int wr = w >> 2;
    int wc = w & 3;

    unsigned int smem_u32;
    asm("{ .reg .u64 t0; cvta.to.shared.u64 t0, %1; cvt.u32.u64 %0, t0; }"
        : "=r"(smem_u32) : "l"(smem));

    int tA_r = tid >> 2, tA_g = tid & 3;
    int tB_r = tid >> 4, tB_g = tid & 15;
    unsigned int aOff0 = (unsigned int)(tA_r * A_LD + tA_g * 8) * 2u;
    unsigned int aOff1 = (unsigned int)((tA_r + 64) * A_LD + tA_g * 8) * 2u;
    unsigned int bOff0 = (unsigned int)(tB_r * B_LD + tB_g * 8) * 2u;
    unsigned int bOff1 = (unsigned int)((tB_r + 16) * B_LD + tB_g * 8) * 2u;

    auto issue_chunk = [&](int kt, int buf) {
        unsigned int aBase = smem_u32 + buf * ABUF;
        unsigned int bBase = smem_u32 + 2 * ABUF + buf * BBUF;
        const __nv_bfloat16* gah = AhV + (long)tA_r * HH + kt * 32 + tA_g * 8;
        const __nv_bfloat16* gal = AlV + (long)tA_r * HH + kt * 32 + tA_g * 8;
        CPA16(aBase + aOff0, gah);
        CPA16(aBase + aOff1, gah + 64 * HH);
        CPA16(aBase + 10240 + aOff0, gal);
        CPA16(aBase + 10240 + aOff1, gal + 64 * HH);
        const __nv_bfloat16* gwh = WhV + (long)(kt * 32 + tB_r) * HH + tB_g * 8;
        const __nv_bfloat16* gwl = WlV + (long)(kt * 32 + tB_r) * HH + tB_g * 8;
        CPA16(bBase + bOff0, gwh);
        CPA16(bBase + bOff1, gwh + 16 * HH);
        CPA16(bBase + 8704 + bOff0, gwl);
        CPA16(bBase + 8704 + bOff1, gwl + 16 * HH);
        asm volatile("cp.async.commit_group;");
    };

    wmma::fragment<wmma::accumulator, 16, 16, 16, float> acc[4][2];
#pragma unroll
    for (int i = 0; i < 4; i++)
#pragma unroll
        for (int j = 0; j < 2; j++) wmma::fill_fragment(acc[i][j], 0.f);

    issue_chunk(0, 0);
    issue_chunk(1, 1);

#pragma unroll
    for (int kt = 0; kt < 4; kt++) {
        if (kt < 3) { asm volatile("cp.async.wait_group 1;" ::: "memory"); }
        else        { asm volatile("cp.async.wait_group 0;" ::: "memory"); }
        __syncthreads();

        int buf = kt & 1;
        const __nv_bfloat16* Ah = (const __nv_bfloat16*)(smem + buf * ABUF);
        const __nv_bfloat16* Al = (const __nv_bfloat16*)(smem + buf * ABUF + 10240);
        const __nv_bfloat16* Bh = (const __nv_bfloat16*)(smem + 2 * ABUF + buf * BBUF);
        const __nv_bfloat16* Bl = (const __nv_bfloat16*)(smem + 2 * ABUF + buf * BBUF + 8704);

#pragma unroll
        for (int ks = 0; ks < 2; ks++) {
            wmma::fragment<wmma::matrix_a, 16, 16, 16, __nv_bfloat16, wmma::row_major> afh[4], afl[4];
            wmma::fragment<wmma::matrix_b, 16, 16, 16, __nv_bfloat16, wmma::row_major> bfh[2], bfl[2];
#pragma unroll
            for (int i = 0; i < 4; i++) {
                wmma::load_matrix_sync(afh[i], &Ah[(wr * 64 + i * 16) * A_LD + ks * 16], A_LD);
                wmma::load_matrix_sync(afl[i], &Al[(wr * 64 + i * 16) * A_LD + ks * 16], A_LD);
            }
#pragma unroll
            for (int j = 0; j < 2; j++) {
                wmma::load_matrix_sync(bfh[j], &Bh[(ks * 16) * B_LD + wc * 32 + j * 16], B_LD);
                wmma::load_matrix_sync(bfl[j], &Bl[(ks * 16) * B_LD + wc * 32 + j * 16], B_LD);
            }
#pragma unroll
            for (int i = 0; i < 4; i++)
#pragma unroll
                for (int j = 0; j < 2; j++) {
                    wmma::mma_sync(acc[i][j], afh[i], bfh[j], acc[i][j]);
                    wmma::mma_sync(acc[i][j], afh[i], bfl[j], acc[i][j]);
                    wmma::mma_sync(acc[i][j], afl[i], bfh[j], acc[i][j]);
                }
        }
        __syncthreads();
        if (kt < 2) issue_chunk(kt + 2, buf);
    }

#pragma unroll
    for (int i = 0; i < 4; i++)
#pragma unroll
        for (int j = 0; j < 2; j++)
            wmma::store_matrix_sync(&Esm[(wr * 64 + i * 16) * E_LD + wc * 32 + j * 16],
                                    acc[i][j], E_LD, wmma::mem_row_major);
    __syncthreads();
}

// packed split-bf16 store of 64 contiguous values
__device__ __forceinline__ void epi_split_store(
    const float* vals, __nv_bfloat16* outHi, __nv_bfloat16* outLo, long rowIdx)
{
    uint32_t hv32[32], lv32[32];
#pragma unroll
    for (int i = 0; i < 32; i++) {
        uint32_t h2 = pkbf2(vals[2 * i], vals[2 * i + 1]);
        float h0 = __uint_as_float(h2 << 16);
        float h1 = __uint_as_float(h2 & 0xffff0000u);
        hv32[i] = h2;
        lv32[i] = pkbf2(vals[2 * i] - h0, vals[2 * i + 1] - h1);
    }
#pragma unroll
    for (int g = 0; g < 8; g++) {
        *(uint4*)&outHi[rowIdx + g * 8] = ((uint4*)hv32)[g];
        *(uint4*)&outLo[rowIdx + g * 8] = ((uint4*)lv32)[g];
    }
}

// ---------------- kernel 2a: mech / Wo GEMM ---------------------------------
template <bool LN_GELU, bool OUT_SPLIT>
__global__ void __launch_bounds__(256, 2) pv_gemm(
    const __nv_bfloat16* __restrict__ Ahi, const __nv_bfloat16* __restrict__ Alo,
    const __nv_bfloat16* __restrict__ Whi, const __nv_bfloat16* __restrict__ Wlo,
    const float* __restrict__ biasB, int bStride,
    const float* __restrict__ gB, const float* __restrict__ betaB,
    float* __restrict__ outF,
    __nv_bfloat16* __restrict__ outHi, __nv_bfloat16* __restrict__ outLo)
{
    extern __shared__ char smem[];
    float* Esm = (float*)smem;

    int v = blockIdx.y;
    int row0 = blockIdx.x * 128;
    const float* bias = biasB + (long)v * bStride;
    int tid = threadIdx.x;

    pv_core(Ahi + ((long)v * BT + row0) * HH, Alo + ((long)v * BT + row0) * HH,
            Whi + (long)v * HS, Wlo + (long)v * HS, smem, tid);

    int row = tid >> 1;
    int ch = (tid & 1) * 64;
    const float* er = Esm + row * E_LD + ch;
    float vals[64];
#pragma unroll
    for (int i = 0; i < 16; i++) {
        float4 x = *(const float4*)&er[i * 4];
        vals[i * 4 + 0] = x.x; vals[i * 4 + 1] = x.y;
        vals[i * 4 + 2] = x.z; vals[i * 4 + 3] = x.w;
    }
#pragma unroll
    for (int i = 0; i < 64; i++) vals[i] += bias[ch + i];

    if (LN_GELU) {
        const float* gp = gB + (long)v * bStride;
        const float* bp = betaB + (long)v * bStride;
        float sum = 0.f, sq = 0.f;
#pragma unroll
        for (int i = 0; i < 64; i++) { sum += vals[i]; sq += vals[i] * vals[i]; }
        sum += __shfl_xor_sync(0xffffffffu, sum, 1);
        sq  += __shfl_xor_sync(0xffffffffu, sq, 1);
        float mu = sum * (1.f / 128.f);
        float var = sq * (1.f / 128.f) - mu * mu;
        float inv = rsqrtf(var + 1e-5f);
#pragma unroll
        for (int i = 0; i < 64; i++) {
            float xn = (vals[i] - mu) * inv * gp[ch + i] + bp[ch + i];
            vals[i] = fast_gelu(xn);
        }
    }

    long rowIdx = ((long)v * BT + row0 + row) * HH + ch;
    if (OUT_SPLIT) {
        epi_split_store(vals, outHi, outLo, rowIdx);
    } else {
#pragma unroll
        for (int i = 0; i < 16; i++) {
            float4 s = make_float4(vals[i * 4], vals[i * 4 + 1], vals[i * 4 + 2], vals[i * 4 + 3]);
            *(float4*)&outF[rowIdx + i * 4] = s;
        }
    }
}

// ---------------- kernel 2b: fused QKV GEMM (z selects matrix) --------------
__global__ void __launch_bounds__(256, 2) pv_gemm_qkv(
    const __nv_bfloat16* __restrict__ Ahi, const __nv_bfloat16* __restrict__ Alo,
    const __nv_bfloat16* __restrict__ Whi3, const __nv_bfloat16* __restrict__ Wlo3,
    const float* __restrict__ bq, const float* __restrict__ bk, const float* __restrict__ bv,
    __nv_bfloat16* __restrict__ qhi, __nv_bfloat16* __restrict__ qlo,
    __nv_bfloat16* __restrict__ khi, __nv_bfloat16* __restrict__ klo,
    __nv_bfloat16* __restrict__ vhi, __nv_bfloat16* __restrict__ vlo)
{
    extern __shared__ char smem[];
    float* Esm = (float*)smem;

    int z = blockIdx.z;
    int v = blockIdx.y;
    int row0 = blockIdx.x * 128;
    int tid = threadIdx.x;

    const float* bias = ((z == 0) ? bq : (z == 1) ? bk : bv) + (long)v * HH;
    __nv_bfloat16* outHi = (z == 0) ? qhi : (z == 1) ? khi : vhi;
    __nv_bfloat16* outLo = (z == 0) ? qlo : (z == 1) ? klo : vlo;
    long wOff = ((long)z * VV + v) * HS;

    pv_core(Ahi + ((long)v * BT + row0) * HH, Alo + ((long)v * BT + row0) * HH,
            Whi3 + wOff, Wlo3 + wOff, smem, tid);

    int row = tid >> 1;
    int ch = (tid & 1) * 64;
    const float* er = Esm + row * E_LD + ch;
    float vals[64];
#pragma unroll
    for (int i = 0; i < 16; i++) {
        float4 x = *(const float4*)&er[i * 4];
        vals[i * 4 + 0] = x.x; vals[i * 4 + 1] = x.y;
        vals[i * 4 + 2] = x.z; vals[i * 4 + 3] = x.w;
    }
#pragma unroll
    for (int i = 0; i < 64; i++) vals[i] += bias[ch + i];

    long rowIdx = ((long)v * BT + row0 + row) * HH + ch;
    epi_split_store(vals, outHi, outLo, rowIdx);
}

// ---------------- kernel 3: flash-style mma attention per (b,v,head) --------
// Inputs are pre-split bf16 hi/lo; staged via cp.async (no conversion work).
#define ALD 24
#define ATTN_SMEM 73728

__global__ void __launch_bounds__(256, 2) attn_mma_kernel(
    const __nv_bfloat16* __restrict__ qhi, const __nv_bfloat16* __restrict__ qlo,
    const __nv_bfloat16* __restrict__ khi, const __nv_bfloat16* __restrict__ klo,
    const __nv_bfloat16* __restrict__ vhi, const __nv_bfloat16* __restrict__ vlo,
    __nv_bfloat16* __restrict__ oHi, __nv_bfloat16* __restrict__ oLo)
{
    extern __shared__ char sm[];

    int g = blockIdx.x;
    int b = g / (VV * NHH);
    int rem = g % (VV * NHH);
    int v = rem / NHH;
    int nh = rem % NHH;
    long base = ((long)v * BT + (long)b * SS) * HH + nh * DHH;

    int tid = threadIdx.x;
    int w = tid >> 5;
    int lane = tid & 31;

    unsigned int smem_u32;
    asm("{ .reg .u64 t0; cvta.to.shared.u64 t0, %1; cvt.u32.u64 %0, t0; }"
        : "=r"(smem_u32) : "l"(sm));

    // ---- stage Q/K/V hi+lo via cp.async (one row per thread, 32B each) ----
    {
        int r = tid;
        long rb = base + (long)r * HH;
        const __nv_bfloat16* srcs[6] = {qhi + rb, qlo + rb, khi + rb,
                                        klo + rb, vhi + rb, vlo + rb};
#pragma unroll
        for (int a = 0; a < 6; a++) {
            unsigned int dst = smem_u32 + a * 12288 + (unsigned int)(r * ALD * 2);
            CPA16(dst, srcs[a]);
            CPA16(dst + 16, srcs[a] + 8);
        }
        asm volatile("cp.async.commit_group;");
        asm volatile("cp.async.wait_group 0;" ::: "memory");
    }
    __syncthreads();

    // per-lane ldmatrix source rows/cols
    int qr = (lane & 7) + ((lane & 8) ? 8 : 0);
    int qc = (lane & 16) ? 8 : 0;                 // A-operand (Q)
    int kr = (lane & 7) + ((lane & 16) ? 8 : 0);
    int kc = (lane & 8) ? 8 : 0;                  // B-operand (K, non-trans)
    int vr = (lane & 7) + ((lane & 8) ? 8 : 0);
    int vc = (lane & 16) ? 8 : 0;                 // B-operand (V, trans)

    // persistent Q fragments: row tiles w*32, w*32+16
    uint32_t qfh[2][4], qfl[2][4];
#pragma unroll
    for (int i = 0; i < 2; i++) {
        unsigned int off = (unsigned int)(((w * 32 + i * 16 + qr) * ALD + qc) * 2);
        ldsm4(qfh[i], smem_u32 + 0     + off);
        ldsm4(qfl[i], smem_u32 + 12288 + off);
    }

    float oacc[2][2][4];
#pragma unroll
    for (int i = 0; i < 2; i++)
#pragma unroll
        for (int n = 0; n < 2; n++)
#pragma unroll
            for (int e = 0; e < 4; e++) oacc[i][n][e] = 0.f;
    float lsum[4] = {0.f, 0.f, 0.f, 0.f};

    const float c0 = 0.25f * 1.4426950408889634f;  // scale * log2(e)

    for (int kt = 0; kt < 16; kt++) {
        uint32_t kh4[4], kl4[4], vh4[4], vl4[4];
        {
            unsigned int koff = (unsigned int)(((kt * 16 + kr) * ALD + kc) * 2);
            unsigned int voff = (unsigned int)(((kt * 16 + vr) * ALD + vc) * 2);
            ldsm4 (kh4, smem_u32 + 24576 + koff);
            ldsm4 (kl4, smem_u32 + 36864 + koff);
            ldsm4t(vh4, smem_u32 + 49152 + voff);
            ldsm4t(vl4, smem_u32 + 61440 + voff);
        }

#pragma unroll
        for (int i = 0; i < 2; i++) {
            float s0[4] = {0.f, 0.f, 0.f, 0.f};
            float s1[4] = {0.f, 0.f, 0.f, 0.f};
            mma16816(s0, qfh[i], &kh4[0]);
            mma16816(s0, qfh[i], &kl4[0]);
            mma16816(s0, qfl[i], &kh4[0]);
            mma16816(s1, qfh[i], &kh4[2]);
            mma16816(s1, qfh[i], &kl4[2]);
            mma16816(s1, qfl[i], &kh4[2]);

            float p00 = ex2a(s0[0] * c0), p01 = ex2a(s0[1] * c0);
            float p02 = ex2a(s0[2] * c0), p03 = ex2a(s0[3] * c0);
            float p10 = ex2a(s1[0] * c0), p11 = ex2a(s1[1] * c0);
            float p12 = ex2a(s1[2] * c0), p13 = ex2a(s1[3] * c0);

            lsum[i * 2 + 0] += (p00 + p01) + (p10 + p11);
            lsum[i * 2 + 1] += (p02 + p03) + (p12 + p13);

            uint32_t ph[4], pl[4];
            ph[0] = pkbf2(p00, p01); ph[1] = pkbf2(p02, p03);
            ph[2] = pkbf2(p10, p11); ph[3] = pkbf2(p12, p13);
            {
                float h0 = __uint_as_float(ph[0] << 16);
                float h1 = __uint_as_float(ph[0] & 0xffff0000u);
                pl[0] = pkbf2(p00 - h0, p01 - h1);
                h0 = __uint_as_float(ph[1] << 16);
                h1 = __uint_as_float(ph[1] & 0xffff0000u);
                pl[1] = pkbf2(p02 - h0, p03 - h1);
                h0 = __uint_as_float(ph[2] << 16);
                h1 = __uint_as_float(ph[2] & 0xffff0000u);
                pl[2] = pkbf2(p10 - h0, p11 - h1);
                h0 = __uint_as_float(ph[3] << 16);
                h1 = __uint_as_float(ph[3] & 0xffff0000u);
                pl[3] = pkbf2(p12 - h0, p13 - h1);
            }

#pragma unroll
            for (int n = 0; n < 2; n++) {
                mma16816(oacc[i][n], ph, &vh4[n * 2]);
                mma16816(oacc[i][n], ph, &vl4[n * 2]);
                mma16816(oacc[i][n], pl, &vh4[n * 2]);
            }
        }
    }

#pragma unroll
    for (int j = 0; j < 4; j++) {
        lsum[j] += __shfl_xor_sync(0xffffffffu, lsum[j], 1);
        lsum[j] += __shfl_xor_sync(0xffffffffu, lsum[j], 2);
    }
    float inv[4];
#pragma unroll
    for (int j = 0; j < 4; j++) inv[j] = 1.f / lsum[j];

    int g2 = lane >> 2, tq = lane & 3;
#pragma unroll
    for (int i = 0; i < 2; i++) {
#pragma unroll
        for (int n = 0; n < 2; n++) {
            float o0 = oacc[i][n][0] * inv[i * 2 + 0];
            float o1 = oacc[i][n][1] * inv[i * 2 + 0];
            float o2 = oacc[i][n][2] * inv[i * 2 + 1];
            float o3 = oacc[i][n][3] * inv[i * 2 + 1];
            int rowA = w * 32 + i * 16 + g2;
            int col = n * 8 + tq * 2;
            long obA = base + (long)rowA * HH + col;
            long obB = obA + 8L * HH;
            uint32_t hA = pkbf2(o0, o1);
            uint32_t hB = pkbf2(o2, o3);
            float hA0 = __uint_as_float(hA << 16), hA1 = __uint_as_float(hA & 0xffff0000u);
            float hB0 = __uint_as_float(hB << 16), hB1 = __uint_as_float(hB & 0xffff0000u);
            *(uint32_t*)&oHi[obA] = hA;
            *(uint32_t*)&oHi[obB] = hB;
            *(uint32_t*)&oLo[obA] = pkbf2(o0 - hA0, o1 - hA1);
            *(uint32_t*)&oLo[obB] = pkbf2(o2 - hB0, o3 - hB1);
        }
    }
}

// ---------------- kernel 4: output head predictions[b,t,v] ------------------
__global__ void __launch_bounds__(256) outhead_kernel(
    const float* __restrict__ o2,
    const float* __restrict__ outW, const float* __restrict__ outB,
    float* __restrict__ pred)
{
    int bt = blockIdx.x;
    int tid = threadIdx.x;
    int v = tid >> 2;
    int part = tid & 3;
    const float* row = o2 + ((long)v * BT + bt) * HH + part * 32;
    const float* w = outW + v * HH + part * 32;
    float acc = 0.f;
#pragma unroll 8
    for (int i = 0; i < 32; i++) acc += row[i] * w[i];
    acc += __shfl_xor_sync(0xffffffffu, acc, 1);
    acc += __shfl_xor_sync(0xffffffffu, acc, 2);
    if (part == 0) pred[bt * VV + v] = acc + outB[v];
}

// ---------------- launch ----------------------------------------------------
extern "C" void kernel_launch(void* const* d_in, const int* in_sizes, int n_in,
                              void* d_out, int out_size) {
    const float* x        = (const float*)d_in[0];
    const float* adjl     = (const float*)d_in[1];
    const float* var_emb  = (const float*)d_in[2];
    const float* temp_emb = (const float*)d_in[3];
    const float* mech_W   = (const float*)d_in[4];
    const float* mech_b   = (const float*)d_in[5];
    const float* ln_g     = (const float*)d_in[6];
    const float* ln_b     = (const float*)d_in[7];
    const float* Wq       = (const float*)d_in[8];
    const float* Wk       = (const float*)d_in[9];
    const float* Wv       = (const float*)d_in[10];
    const float* Wo       = (const float*)d_in[11];
    const float* bq       = (const float*)d_in[12];
    const float* bk       = (const float*)d_in[13];
    const float* bv       = (const float*)d_in[14];
    const float* bo       = (const float*)d_in[15];
    const float* out_W    = (const float*)d_in[16];
    const float* out_b    = (const float*)d_in[17];
    float* pred = (float*)d_out;

    float *adj, *z0;
    __nv_bfloat16 *Whi, *Wlo, *zhi0, *zlo0, *zhi1, *zlo1, *ohi, *olo;
    __nv_bfloat16 *qhi, *qlo, *khi, *klo, *vhi, *vlo;
    cudaGetSymbolAddress((void**)&adj, g_adj);
    cudaGetSymbolAddress((void**)&Whi, g_Whi);
    cudaGetSymbolAddress((void**)&Wlo, g_Wlo);
    cudaGetSymbolAddress((void**)&zhi0, g_zhi0);
    cudaGetSymbolAddress((void**)&zlo0, g_zlo0);
    cudaGetSymbolAddress((void**)&zhi1, g_zhi1);
    cudaGetSymbolAddress((void**)&zlo1, g_zlo1);
    cudaGetSymbolAddress((void**)&ohi, g_ohi);
    cudaGetSymbolAddress((void**)&olo, g_olo);
    cudaGetSymbolAddress((void**)&qhi, g_qhi);
    cudaGetSymbolAddress((void**)&qlo, g_qlo);
    cudaGetSymbolAddress((void**)&khi, g_khi);
    cudaGetSymbolAddress((void**)&klo, g_klo);
    cudaGetSymbolAddress((void**)&vhi, g_vhi);
    cudaGetSymbolAddress((void**)&vlo, g_vlo);
    cudaGetSymbolAddress((void**)&z0, g_z0);

    static bool attr_done = false;
    if (!attr_done) {
        cudaFuncSetAttribute((const void*)pv_gemm<true, true>,
                             cudaFuncAttributeMaxDynamicSharedMemorySize, PV_SMEM_BYTES);
        cudaFuncSetAttribute((const void*)pv_gemm<false, false>,
                             cudaFuncAttributeMaxDynamicSharedMemorySize, PV_SMEM_BYTES);
        cudaFuncSetAttribute((const void*)pv_gemm_qkv,
                             cudaFuncAttributeMaxDynamicSharedMemorySize, PV_SMEM_BYTES);
        cudaFuncSetAttribute((const void*)attn_mma_kernel,
                             cudaFuncAttributeMaxDynamicSharedMemorySize, ATTN_SMEM);
        attr_done = true;
    }

    int nadj = VV * VV * LP1;
    sigmoid_kernel<<<(nadj + 255) / 256, 256>>>(adjl, adj, nadj);

    long nw = 7L * VV * HS;
    split_weights_kernel<<<(int)((nw + 255) / 256), 256>>>(mech_W, Wq, Wk, Wv, Wo, Whi, Wlo);

    causal_input_kernel<<<BT, 128>>>(x, var_emb, temp_emb, adj, zhi0, zlo0);

    dim3 gg(BT / 128, VV);
    const long WSZ = (long)VV * HS;
    pv_gemm<true, true><<<gg, 256, PV_SMEM_BYTES>>>(
        zhi0, zlo0, Whi + 0 * WSZ, Wlo + 0 * WSZ, mech_b + 0 * HH, NLL * HH,
        ln_g + 0 * HH, ln_b + 0 * HH, nullptr, zhi1, zlo1);
    pv_gemm<true, true><<<gg, 256, PV_SMEM_BYTES>>>(
        zhi1, zlo1, Whi + 1 * WSZ, Wlo + 1 * WSZ, mech_b + 1 * HH, NLL * HH,
        ln_g + 1 * HH, ln_b + 1 * HH, nullptr, zhi0, zlo0);
    pv_gemm<true, true><<<gg, 256, PV_SMEM_BYTES>>>(
        zhi0, zlo0, Whi + 2 * WSZ, Wlo + 2 * WSZ, mech_b + 2 * HH, NLL * HH,
        ln_g + 2 * HH, ln_b + 2 * HH, nullptr, zhi1, zlo1);
    // fused QKV (z = 0,1,2 -> Wq,Wk,Wv), split-bf16 outputs
    pv_gemm_qkv<<<dim3(BT / 128, VV, 3), 256, PV_SMEM_BYTES>>>(
        zhi1, zlo1, Whi + 3 * WSZ, Wlo + 3 * WSZ, bq, bk, bv,
        qhi, qlo, khi, klo, vhi, vlo);
    attn_mma_kernel<<<BB * VV * NHH, 256, ATTN_SMEM>>>(
        qhi, qlo, khi, klo, vhi, vlo, ohi, olo);
    pv_gemm<false, false><<<gg, 256, PV_SMEM_BYTES>>>(
        ohi, olo, Whi + 6 * WSZ, Wlo + 6 * WSZ, bo, HH,
        nullptr, nullptr, z0, nullptr, nullptr);
    outhead_kernel<<<BT, 256>>>(z0, out_W, out_b, pred);
}